// round 10
// baseline (speedup 1.0000x reference)
#include <cuda_runtime.h>
#include <cuda_bf16.h>
#include <cuda_fp16.h>
#include <cstdint>

// ---------------------------------------------------------------------------
// AdaptiveMixing on GB300 (compute_103 portable path):
//   params = query @ Wp + bp   [3600 x 32768]   fp16 2-pass mma.sync
//   per (tok,grp): x@M -> LN -> relu -> S@ -> LN -> relu -> Z   (fp32 f32x2)
//   out = Z @ Wo + bo + query  [3600 x 256]     fp16 2-pass mma.sync
// R9: 3-stage cp.async ring in the GEMM (hides DRAM latency; 1 barrier/chunk).
// ---------------------------------------------------------------------------
#define NTOK   3600
#define QDIM   256
#define PCOLS  32768
#define TOTALP 8192
#define INP    32
#define EIN    64
#define SPLITK 32

typedef unsigned long long ull;
typedef __half fp16;

// ------------------------- device scratch (no allocs) ----------------------
__device__ float g_params[(size_t)NTOK * PCOLS];
__device__ fp16  g_qhi[(size_t)NTOK * QDIM];
__device__ fp16  g_qlo[(size_t)NTOK * QDIM];
__device__ fp16  g_wpT[(size_t)PCOLS * QDIM];
__device__ fp16  g_woT[(size_t)QDIM * PCOLS];
__device__ fp16  g_zhi[(size_t)NTOK * PCOLS];
__device__ fp16  g_zlo[(size_t)NTOK * PCOLS];
__device__ float g_part[(size_t)SPLITK * NTOK * QDIM];

// ----------------------------- helpers -------------------------------------
__device__ __forceinline__ ull pack2(float lo, float hi) {
    ull r; asm("mov.b64 %0, {%1,%2};" : "=l"(r) : "f"(lo), "f"(hi)); return r;
}
__device__ __forceinline__ void unpack2(ull v, float& lo, float& hi) {
    asm("mov.b64 {%0,%1}, %2;" : "=f"(lo), "=f"(hi) : "l"(v));
}
__device__ __forceinline__ void fma2(ull& d, ull a, ull b) {
    asm("fma.rn.f32x2 %0, %1, %2, %0;" : "+l"(d) : "l"(a), "l"(b));
}
__device__ __forceinline__ void f2hiloH(float v, fp16& h, fp16& l) {
    h = __float2half_rn(v);
    l = __float2half_rn(v - __half2float(h));
}
__device__ __forceinline__ unsigned hpk(fp16 a, fp16 b) {
    return (unsigned)__half_as_ushort(a) | ((unsigned)__half_as_ushort(b) << 16);
}
__device__ __forceinline__ uint32_t smem_u32(const void* p) {
    uint32_t a;
    asm("{ .reg .u64 t; cvta.to.shared.u64 t, %1; cvt.u32.u64 %0, t; }" : "=r"(a) : "l"(p));
    return a;
}
__device__ __forceinline__ void ldsm4(uint32_t& r0, uint32_t& r1, uint32_t& r2, uint32_t& r3,
                                      uint32_t addr) {
    asm volatile("ldmatrix.sync.aligned.m8n8.x4.shared.b16 {%0,%1,%2,%3}, [%4];"
                 : "=r"(r0), "=r"(r1), "=r"(r2), "=r"(r3) : "r"(addr));
}
__device__ __forceinline__ void mma_f16(float* c, const uint32_t* a, const uint32_t* b) {
    asm volatile(
        "mma.sync.aligned.m16n8k16.row.col.f32.f16.f16.f32 "
        "{%0,%1,%2,%3}, {%4,%5,%6,%7}, {%8,%9}, {%0,%1,%2,%3};"
        : "+f"(c[0]), "+f"(c[1]), "+f"(c[2]), "+f"(c[3])
        : "r"(a[0]), "r"(a[1]), "r"(a[2]), "r"(a[3]), "r"(b[0]), "r"(b[1]));
}
__device__ __forceinline__ void cpa16(uint32_t dst, const void* src, int sz) {
    asm volatile("cp.async.cg.shared.global [%0], [%1], 16, %2;"
                 :: "r"(dst), "l"(src), "r"(sz) : "memory");
}
#define CP_COMMIT() asm volatile("cp.async.commit_group;" ::: "memory")
#define CP_WAIT(n)  asm volatile("cp.async.wait_group %0;" :: "n"(n) : "memory")

// ---------------------------------------------------------------------------
// Conversion kernels
// ---------------------------------------------------------------------------
__global__ void convQf16(const float* __restrict__ q, fp16* __restrict__ hi, fp16* __restrict__ lo) {
    int i = blockIdx.x * 256 + threadIdx.x;
    if (i >= NTOK * QDIM / 4) return;
    float4 v = ((const float4*)q)[i];
    fp16 h0,l0,h1,l1,h2,l2,h3,l3;
    f2hiloH(v.x,h0,l0); f2hiloH(v.y,h1,l1); f2hiloH(v.z,h2,l2); f2hiloH(v.w,h3,l3);
    ((uint2*)hi)[i] = make_uint2(hpk(h0,h1), hpk(h2,h3));
    ((uint2*)lo)[i] = make_uint2(hpk(l0,l1), hpk(l2,l3));
}

// transpose + convert to single fp16: in [R][C] f32 -> out[C][R]
__global__ void transConvF16(const float* __restrict__ in, fp16* __restrict__ o,
                             int R, int C) {
    __shared__ float tile[32][33];
    int c0 = blockIdx.x * 32, r0 = blockIdx.y * 32;
    int tx = threadIdx.x, ty = threadIdx.y;    // 32 x 8
    #pragma unroll
    for (int i = 0; i < 4; i++)
        tile[ty + 8 * i][tx] = in[(size_t)(r0 + ty + 8 * i) * C + c0 + tx];
    __syncthreads();
    #pragma unroll
    for (int i = 0; i < 4; i++) {
        float v = tile[tx][ty + 8 * i];
        o[(size_t)(c0 + ty + 8 * i) * R + r0 + tx] = __float2half_rn(v);
    }
}

// ---------------------------------------------------------------------------
// fp16 2-pass GEMM: C = (Ah + Al) * B^T, A split hi/lo, B single.
// 128x128 CTA tile, BK=32, 8 warps (4x2), warp tile 32x64.
// smem row pitch 40 halves (80B) -> conflict-free ldmatrix.
// 3-stage cp.async ring: waited stage is 2 chunks old -> latency hidden,
// and loads target a third buffer -> single barrier per chunk.
// ---------------------------------------------------------------------------
#define TILE_B   10240                   // 128 rows * 40 * 2B
#define STAGE_B2 (3 * TILE_B)            // Ah, Al, B per stage
#define GSMEM2   (3 * STAGE_B2)          // 92160 (3 stages)

__global__ __launch_bounds__(256, 2)
void gemm_mma2(const fp16* __restrict__ Ahi, const fp16* __restrict__ Alo,
               const fp16* __restrict__ B,
               float* __restrict__ C, const float* __restrict__ bias,
               int M, int lda, int ldb, int ldc, int nChunks, int partStride)
{
    extern __shared__ char smem[];
    const uint32_t sm0 = smem_u32(smem);
    const int t = threadIdx.x, lane = t & 31, w = t >> 5;
    const int wr = w & 3, wc = w >> 2;
    const int mrow0 = blockIdx.y * 128;
    const int n0 = blockIdx.x * 128;
    const int k0 = blockIdx.z * nChunks * 32;
    float* Cb = C + (size_t)blockIdx.z * partStride;

    const int row0_ = t >> 2, seg0 = t & 3;
    const int row1_ = (t + 256) >> 2, seg1 = (t + 256) & 3;
    const uint32_t so0 = (uint32_t)(row0_ * 40 + seg0 * 8) * 2;
    const uint32_t so1 = (uint32_t)(row1_ * 40 + seg1 * 8) * 2;
    const int okA0 = ((mrow0 + row0_) < M) ? 16 : 0;
    const int okA1 = ((mrow0 + row1_) < M) ? 16 : 0;
    const size_t gaBase0 = (size_t)(mrow0 + row0_) * lda + seg0 * 8 + k0;
    const size_t gaBase1 = (size_t)(mrow0 + row1_) * lda + seg1 * 8 + k0;
    const size_t gbBase0 = (size_t)(n0 + row0_) * ldb + seg0 * 8 + k0;
    const size_t gbBase1 = (size_t)(n0 + row1_) * ldb + seg1 * 8 + k0;

    const int q = lane >> 3, r8 = lane & 7;
    const uint32_t aoff = (uint32_t)((wr * 32 + r8 + ((q & 1) << 3)) * 40 + ((q >> 1) << 3)) * 2;
    const uint32_t boff = (uint32_t)((wc * 64 + r8 + ((q >> 1) << 3)) * 40 + ((q & 1) << 3)) * 2;

    float c[2][8][4];
    #pragma unroll
    for (int mt = 0; mt < 2; mt++)
        #pragma unroll
        for (int nt = 0; nt < 8; nt++)
            #pragma unroll
            for (int j = 0; j < 4; j++) c[mt][nt][j] = 0.f;

    auto stageLoad = [&](int stage, int kk) {
        uint32_t sb = sm0 + stage * STAGE_B2;
        cpa16(sb + 0 * TILE_B + so0, Ahi + gaBase0 + kk, okA0);
        cpa16(sb + 1 * TILE_B + so0, Alo + gaBase0 + kk, okA0);
        cpa16(sb + 2 * TILE_B + so0, B   + gbBase0 + kk, 16);
        cpa16(sb + 0 * TILE_B + so1, Ahi + gaBase1 + kk, okA1);
        cpa16(sb + 1 * TILE_B + so1, Alo + gaBase1 + kk, okA1);
        cpa16(sb + 2 * TILE_B + so1, B   + gbBase1 + kk, 16);
        CP_COMMIT();
    };

    // prologue: 2 stages in flight
    stageLoad(0, 0);
    if (nChunks > 1) stageLoad(1, 32);

    int buf = 0;
    for (int ch = 0; ch < nChunks; ch++) {
        if (ch + 1 < nChunks) { CP_WAIT(1); } else { CP_WAIT(0); }
        __syncthreads();
        if (ch + 2 < nChunks) {
            int nb = buf + 2; if (nb >= 3) nb -= 3;
            stageLoad(nb, (ch + 2) * 32);
        }

        const uint32_t base = sm0 + buf * STAGE_B2;
        #pragma unroll
        for (int ks = 0; ks < 2; ks++) {
            uint32_t ah[2][4], al2[2][4];
            #pragma unroll
            for (int mt = 0; mt < 2; mt++) {
                uint32_t aA = base + aoff + mt * (16 * 80) + ks * 32;
                ldsm4(ah[mt][0], ah[mt][1], ah[mt][2], ah[mt][3], aA);
                ldsm4(al2[mt][0], al2[mt][1], al2[mt][2], al2[mt][3], aA + TILE_B);
            }
            #pragma unroll
            for (int g = 0; g < 4; g++) {
                uint32_t bh[4];
                uint32_t aB = base + 2 * TILE_B + boff + g * (16 * 80) + ks * 32;
                ldsm4(bh[0], bh[1], bh[2], bh[3], aB);
                #pragma unroll
                for (int mt = 0; mt < 2; mt++) {
                    mma_f16(c[mt][2*g],   ah[mt],  &bh[0]);
                    mma_f16(c[mt][2*g+1], ah[mt],  &bh[2]);
                    mma_f16(c[mt][2*g],   al2[mt], &bh[0]);
                    mma_f16(c[mt][2*g+1], al2[mt], &bh[2]);
                }
            }
        }
        if (++buf == 3) buf = 0;
    }

    const int crow = mrow0 + wr * 32 + (lane >> 2);
    const int ccol = n0 + wc * 64 + (lane & 3) * 2;
    #pragma unroll
    for (int mt = 0; mt < 2; mt++) {
        #pragma unroll
        for (int nt = 0; nt < 8; nt++) {
            int col = ccol + nt * 8;
            float b0 = 0.f, b1 = 0.f;
            if (bias) { b0 = bias[col]; b1 = bias[col + 1]; }
            int r0 = crow + mt * 16;
            if (r0 < M) {
                float2 v = make_float2(c[mt][nt][0] + b0, c[mt][nt][1] + b1);
                *(float2*)(Cb + (size_t)r0 * ldc + col) = v;
            }
            int r1 = r0 + 8;
            if (r1 < M) {
                float2 v = make_float2(c[mt][nt][2] + b0, c[mt][nt][3] + b1);
                *(float2*)(Cb + (size_t)r1 * ldc + col) = v;
            }
        }
    }
}

// ---------------------------------------------------------------------------
// Block reduction of (sum, sumsq) over 128 threads / 4 warps.
// ---------------------------------------------------------------------------
__device__ __forceinline__ void blockReduce2_128(float& s, float& q, float* red) {
    #pragma unroll
    for (int o = 16; o > 0; o >>= 1) {
        s += __shfl_xor_sync(0xffffffffu, s, o);
        q += __shfl_xor_sync(0xffffffffu, q, o);
    }
    const int t = threadIdx.x;
    if ((t & 31) == 0) { red[t >> 5] = s; red[4 + (t >> 5)] = q; }
    __syncthreads();
    s = red[0] + red[1] + red[2] + red[3];
    q = red[4] + red[5] + red[6] + red[7];
    __syncthreads();
}

// ---------------------------------------------------------------------------
// Fused middle: 128 threads/CTA; outputs Z as fp16 hi/lo
// ---------------------------------------------------------------------------
__global__ __launch_bounds__(128)
void midkernel(const float* __restrict__ x, const float* __restrict__ params,
               fp16* __restrict__ Zhi, fp16* __restrict__ Zlo)
{
    __shared__ float smem[12288];
    float* sX  = smem;
    float* sM  = smem + 2048;
    float* sST = smem + 6144;
    float* sO1 = smem + 10240;
    float* red = smem;

    const int ng = blockIdx.x;
    const int t  = threadIdx.x;
    const float* xb = x + (size_t)ng * (INP * EIN);
    const float* pb = params + (size_t)(ng >> 2) * PCOLS + (size_t)(ng & 3) * TOTALP;

    {
        const float4* x4 = (const float4*)xb;
        const float4* m4 = (const float4*)pb;
        const float4* s4 = (const float4*)(pb + 4096);
        ((float4*)sX)[t]       = x4[t];
        ((float4*)sX)[t + 128] = x4[t + 128];
        ((float4*)sX)[t + 256] = x4[t + 256];
        ((float4*)sX)[t + 384] = x4[t + 384];
        #pragma unroll
        for (int i = 0; i < 8; i++)
            ((float4*)sM)[t + 128 * i] = m4[t + 128 * i];
        #pragma unroll
        for (int i = 0; i < 8; i++) {
            int idx = t + 128 * i;
            float4 v = s4[idx];
            int qq = idx >> 3;
            int p4 = (idx & 7) << 2;
            sST[(p4 + 0) * 128 + qq] = v.x;
            sST[(p4 + 1) * 128 + qq] = v.y;
            sST[(p4 + 2) * 128 + qq] = v.z;
            sST[(p4 + 3) * 128 + qq] = v.w;
        }
    }
    __syncthreads();

    const int p0 = (t >> 3) << 1;
    const int og = (t & 7) << 3;
    ull acc1[2][4];
    #pragma unroll
    for (int i = 0; i < 2; i++)
        #pragma unroll
        for (int j = 0; j < 4; j++) acc1[i][j] = 0ull;

    #pragma unroll 4
    for (int cix = 0; cix < 64; cix++) {
        float xv0 = sX[p0 * 64 + cix];
        float xv1 = sX[(p0 + 1) * 64 + cix];
        ull x0 = pack2(xv0, xv0);
        ull x1 = pack2(xv1, xv1);
        const ulonglong2* mp = (const ulonglong2*)(sM + cix * 64 + og);
        ulonglong2 m0 = mp[0], m1 = mp[1];
        fma2(acc1[0][0], x0, m0.x); fma2(acc1[0][1], x0, m0.y);
        fma2(acc1[0][2], x0, m1.x); fma2(acc1[0][3], x0, m1.y);
        fma2(acc1[1][0], x1, m0.x); fma2(acc1[1][1], x1, m0.y);
        fma2(acc1[1][2], x1, m1.x); fma2(acc1[1][3], x1, m1.y);
    }
    float v1[2][8];
    float s1 = 0.f, q1 = 0.f;
    #pragma unroll
    for (int i = 0; i < 2; i++) {
        unpack2(acc1[i][0], v1[i][0], v1[i][1]); unpack2(acc1[i][1], v1[i][2], v1[i][3]);
        unpack2(acc1[i][2], v1[i][4], v1[i][5]); unpack2(acc1[i][3], v1[i][6], v1[i][7]);
        #pragma unroll
        for (int j = 0; j < 8; j++) { s1 += v1[i][j]; q1 += v1[i][j] * v1[i][j]; }
    }
    __syncthreads();
    blockReduce2_128(s1, q1, red);
    {
        float mean = s1 * (1.f / 2048.f);
        float var  = q1 * (1.f / 2048.f) - mean * mean;
        float rs   = rsqrtf(var + 1e-5f);
        #pragma unroll
        for (int i = 0; i < 2; i++)
            #pragma unroll
            for (int j = 0; j < 8; j++)
                sO1[(p0 + i) * 64 + og + j] = fmaxf((v1[i][j] - mean) * rs, 0.f);
    }
    __syncthreads();

    const int ty = t >> 3;
    const int tx = t & 7;
    ull acc2[8][4];
    #pragma unroll
    for (int i = 0; i < 8; i++)
        #pragma unroll
        for (int j = 0; j < 4; j++) acc2[i][j] = 0ull;

    #pragma unroll 2
    for (int p = 0; p < 32; p++) {
        const float4* stp = (const float4*)(sST + p * 128 + ty * 8);
        float4 sv0 = stp[0], sv1 = stp[1];
        const ulonglong2* op = (const ulonglong2*)(sO1 + p * 64 + tx * 8);
        ulonglong2 b0 = op[0], b1 = op[1];
        float svv[8] = {sv0.x, sv0.y, sv0.z, sv0.w, sv1.x, sv1.y, sv1.z, sv1.w};
        #pragma unroll
        for (int i = 0; i < 8; i++) {
            ull sp = pack2(svv[i], svv[i]);
            fma2(acc2[i][0], sp, b0.x); fma2(acc2[i][1], sp, b0.y);
            fma2(acc2[i][2], sp, b1.x); fma2(acc2[i][3], sp, b1.y);
        }
    }
    float v2[8][8];
    float s2 = 0.f, q2 = 0.f;
    #pragma unroll
    for (int i = 0; i < 8; i++) {
        unpack2(acc2[i][0], v2[i][0], v2[i][1]); unpack2(acc2[i][1], v2[i][2], v2[i][3]);
        unpack2(acc2[i][2], v2[i][4], v2[i][5]); unpack2(acc2[i][3], v2[i][6], v2[i][7]);
        #pragma unroll
        for (int j = 0; j < 8; j++) { s2 += v2[i][j]; q2 += v2[i][j] * v2[i][j]; }
    }
    blockReduce2_128(s2, q2, red);
    float mean2 = s2 * (1.f / 8192.f);
    float var2  = q2 * (1.f / 8192.f) - mean2 * mean2;
    float rs2   = rsqrtf(var2 + 1e-5f);

    const size_t zbase = (size_t)(ng >> 2) * PCOLS + (size_t)(ng & 3) * TOTALP;
    #pragma unroll
    for (int i = 0; i < 8; i++) {
        const int qrow = ty * 8 + i;
        fp16 h[8], l[8];
        #pragma unroll
        for (int j = 0; j < 8; j++) {
            float o = fmaxf((v2[i][j] - mean2) * rs2, 0.f);
            f2hiloH(o, h[j], l[j]);
        }
        size_t off = zbase + (size_t)qrow * 64 + tx * 8;
        *(uint4*)(Zhi + off) = make_uint4(hpk(h[0],h[1]), hpk(h[2],h[3]), hpk(h[4],h[5]), hpk(h[6],h[7]));
        *(uint4*)(Zlo + off) = make_uint4(hpk(l[0],l[1]), hpk(l[2],l[3]), hpk(l[4],l[5]), hpk(l[6],l[7]));
    }
}

// ---------------------------------------------------------------------------
__global__ void finalReduce(const float* __restrict__ part,
                            const float* __restrict__ query,
                            const float* __restrict__ bo,
                            float* __restrict__ out)
{
    int i = blockIdx.x * 256 + threadIdx.x;
    if (i >= NTOK * QDIM) return;
    float s = query[i] + bo[i & (QDIM - 1)];
    #pragma unroll
    for (int z = 0; z < SPLITK; z++)
        s += part[(size_t)z * NTOK * QDIM + i];
    out[i] = s;
}

// ---------------------------------------------------------------------------
extern "C" void kernel_launch(void* const* d_in, const int* in_sizes, int n_in,
                              void* d_out, int out_size)
{
    const float* x     = (const float*)d_in[0];
    const float* query = (const float*)d_in[1];
    const float* Wp    = (const float*)d_in[2];
    const float* bp    = (const float*)d_in[3];
    const float* Wo    = (const float*)d_in[4];
    const float* bo    = (const float*)d_in[5];
    float* out = (float*)d_out;

    float *pParams, *pPart;
    fp16 *pQh, *pQl, *pWpT, *pWoT, *pZh, *pZl;
    cudaGetSymbolAddress((void**)&pParams, g_params);
    cudaGetSymbolAddress((void**)&pPart, g_part);
    cudaGetSymbolAddress((void**)&pQh, g_qhi);
    cudaGetSymbolAddress((void**)&pQl, g_qlo);
    cudaGetSymbolAddress((void**)&pWpT, g_wpT);
    cudaGetSymbolAddress((void**)&pWoT, g_woT);
    cudaGetSymbolAddress((void**)&pZh, g_zhi);
    cudaGetSymbolAddress((void**)&pZl, g_zlo);

    static cudaStream_t s1 = nullptr, s2 = nullptr;
    static cudaEvent_t evRoot = nullptr, evWp = nullptr, evWo = nullptr;
    if (!s1) {
        cudaStreamCreateWithFlags(&s1, cudaStreamNonBlocking);
        cudaStreamCreateWithFlags(&s2, cudaStreamNonBlocking);
        cudaEventCreateWithFlags(&evRoot, cudaEventDisableTiming);
        cudaEventCreateWithFlags(&evWp, cudaEventDisableTiming);
        cudaEventCreateWithFlags(&evWo, cudaEventDisableTiming);
        cudaFuncSetAttribute(gemm_mma2, cudaFuncAttributeMaxDynamicSharedMemorySize, GSMEM2);
    }

    cudaEventRecord(evRoot, 0);
    cudaStreamWaitEvent(s1, evRoot, 0);
    cudaStreamWaitEvent(s2, evRoot, 0);

    convQf16<<<(NTOK * QDIM / 4 + 255) / 256, 256>>>(query, pQh, pQl);
    transConvF16<<<dim3(PCOLS / 32, QDIM / 32), dim3(32, 8), 0, s1>>>(Wp, pWpT, QDIM, PCOLS);
    transConvF16<<<dim3(QDIM / 32, PCOLS / 32), dim3(32, 8), 0, s2>>>(Wo, pWoT, PCOLS, QDIM);

    cudaEventRecord(evWp, s1);
    cudaStreamWaitEvent(0, evWp, 0);

    // GEMM1: params = q @ Wp + bp   (fp16 2-pass, K=256 -> 8 chunks of 32)
    gemm_mma2<<<dim3(PCOLS / 128, 29, 1), 256, GSMEM2>>>(
        pQh, pQl, pWpT, pParams, bp, NTOK, QDIM, QDIM, PCOLS, 8, 0);

    midkernel<<<NTOK * 4, 128>>>(x, pParams, pZh, pZl);

    cudaEventRecord(evWo, s2);
    cudaStreamWaitEvent(0, evWo, 0);

    // GEMM3: part[z] = Z[:, z*1024:(z+1)*1024] @ Wo-chunk  (fp16 2-pass)
    gemm_mma2<<<dim3(QDIM / 128, 29, SPLITK), 256, GSMEM2>>>(
        pZh, pZl, pWoT, pPart, nullptr,
        NTOK, PCOLS, PCOLS, QDIM, (PCOLS / SPLITK) / 32, (int)((size_t)NTOK * QDIM));

    finalReduce<<<(NTOK * QDIM + 255) / 256, 256>>>(pPart, query, bo, out);
}

// round 11
// speedup vs baseline: 1.1033x; 1.1033x over previous
#include <cuda_runtime.h>
#include <cuda_bf16.h>
#include <cuda_fp16.h>
#include <cstdint>

// ---------------------------------------------------------------------------
// AdaptiveMixing on GB300 (compute_103 portable path):
//   params = query @ Wp + bp   [3600 x 32768]   fp16 2-pass mma.sync
//   per (tok,grp): x@M -> LN -> relu -> S@ -> LN -> relu -> Z   (fp32 f32x2)
//   out = Z @ Wo + bo + query  [3600 x 256]     fp16 1-pass mma.sync
// R11: revert GEMM pipeline to R8 (2-stage, prefetch-before-wait — proven);
//      GEMM3 single-pass (Z single fp16): half the MMAs, half Z traffic.
// Error model (calibrated): each fp16 operand truncation ~2.4-2.8e-4;
// total ~4.1e-4 vs 1e-3 gate.
// ---------------------------------------------------------------------------
#define NTOK   3600
#define QDIM   256
#define PCOLS  32768
#define TOTALP 8192
#define INP    32
#define EIN    64
#define SPLITK 32

typedef unsigned long long ull;
typedef __half fp16;

// ------------------------- device scratch (no allocs) ----------------------
__device__ float g_params[(size_t)NTOK * PCOLS];
__device__ fp16  g_qhi[(size_t)NTOK * QDIM];
__device__ fp16  g_qlo[(size_t)NTOK * QDIM];
__device__ fp16  g_wpT[(size_t)PCOLS * QDIM];
__device__ fp16  g_woT[(size_t)QDIM * PCOLS];
__device__ fp16  g_z[(size_t)NTOK * PCOLS];
__device__ float g_part[(size_t)SPLITK * NTOK * QDIM];

// ----------------------------- helpers -------------------------------------
__device__ __forceinline__ ull pack2(float lo, float hi) {
    ull r; asm("mov.b64 %0, {%1,%2};" : "=l"(r) : "f"(lo), "f"(hi)); return r;
}
__device__ __forceinline__ void unpack2(ull v, float& lo, float& hi) {
    asm("mov.b64 {%0,%1}, %2;" : "=f"(lo), "=f"(hi) : "l"(v));
}
__device__ __forceinline__ void fma2(ull& d, ull a, ull b) {
    asm("fma.rn.f32x2 %0, %1, %2, %0;" : "+l"(d) : "l"(a), "l"(b));
}
__device__ __forceinline__ void f2hiloH(float v, fp16& h, fp16& l) {
    h = __float2half_rn(v);
    l = __float2half_rn(v - __half2float(h));
}
__device__ __forceinline__ unsigned hpk(fp16 a, fp16 b) {
    return (unsigned)__half_as_ushort(a) | ((unsigned)__half_as_ushort(b) << 16);
}
__device__ __forceinline__ uint32_t smem_u32(const void* p) {
    uint32_t a;
    asm("{ .reg .u64 t; cvta.to.shared.u64 t, %1; cvt.u32.u64 %0, t; }" : "=r"(a) : "l"(p));
    return a;
}
__device__ __forceinline__ void ldsm4(uint32_t& r0, uint32_t& r1, uint32_t& r2, uint32_t& r3,
                                      uint32_t addr) {
    asm volatile("ldmatrix.sync.aligned.m8n8.x4.shared.b16 {%0,%1,%2,%3}, [%4];"
                 : "=r"(r0), "=r"(r1), "=r"(r2), "=r"(r3) : "r"(addr));
}
__device__ __forceinline__ void mma_f16(float* c, const uint32_t* a, const uint32_t* b) {
    asm volatile(
        "mma.sync.aligned.m16n8k16.row.col.f32.f16.f16.f32 "
        "{%0,%1,%2,%3}, {%4,%5,%6,%7}, {%8,%9}, {%0,%1,%2,%3};"
        : "+f"(c[0]), "+f"(c[1]), "+f"(c[2]), "+f"(c[3])
        : "r"(a[0]), "r"(a[1]), "r"(a[2]), "r"(a[3]), "r"(b[0]), "r"(b[1]));
}
__device__ __forceinline__ void cpa16(uint32_t dst, const void* src, int sz) {
    asm volatile("cp.async.cg.shared.global [%0], [%1], 16, %2;"
                 :: "r"(dst), "l"(src), "r"(sz) : "memory");
}
#define CP_COMMIT() asm volatile("cp.async.commit_group;" ::: "memory")
#define CP_WAIT(n)  asm volatile("cp.async.wait_group %0;" :: "n"(n) : "memory")

// ---------------------------------------------------------------------------
// Conversion kernels
// ---------------------------------------------------------------------------
__global__ void convQf16(const float* __restrict__ q, fp16* __restrict__ hi, fp16* __restrict__ lo) {
    int i = blockIdx.x * 256 + threadIdx.x;
    if (i >= NTOK * QDIM / 4) return;
    float4 v = ((const float4*)q)[i];
    fp16 h0,l0,h1,l1,h2,l2,h3,l3;
    f2hiloH(v.x,h0,l0); f2hiloH(v.y,h1,l1); f2hiloH(v.z,h2,l2); f2hiloH(v.w,h3,l3);
    ((uint2*)hi)[i] = make_uint2(hpk(h0,h1), hpk(h2,h3));
    ((uint2*)lo)[i] = make_uint2(hpk(l0,l1), hpk(l2,l3));
}

// transpose + convert to single fp16: in [R][C] f32 -> out[C][R]
__global__ void transConvF16(const float* __restrict__ in, fp16* __restrict__ o,
                             int R, int C) {
    __shared__ float tile[32][33];
    int c0 = blockIdx.x * 32, r0 = blockIdx.y * 32;
    int tx = threadIdx.x, ty = threadIdx.y;    // 32 x 8
    #pragma unroll
    for (int i = 0; i < 4; i++)
        tile[ty + 8 * i][tx] = in[(size_t)(r0 + ty + 8 * i) * C + c0 + tx];
    __syncthreads();
    #pragma unroll
    for (int i = 0; i < 4; i++) {
        float v = tile[tx][ty + 8 * i];
        o[(size_t)(c0 + ty + 8 * i) * R + r0 + tx] = __float2half_rn(v);
    }
}

// ---------------------------------------------------------------------------
// fp16 GEMM via mma.sync, templated on A passes (TWO=split hi/lo, else single).
// 128x128 CTA tile, BK=32, 8 warps (4x2), warp tile 32x64.
// smem row pitch 40 halves (80B) -> conflict-free ldmatrix.
// 2-stage cp.async, prefetch-before-wait (effective depth 2; R8-proven).
// ---------------------------------------------------------------------------
#define TILE_B   10240                   // 128 rows * 40 * 2B

template<bool TWO>
__global__ __launch_bounds__(256, 2)
void gemm_f16(const fp16* __restrict__ Ahi, const fp16* __restrict__ Alo,
              const fp16* __restrict__ B,
              float* __restrict__ C, const float* __restrict__ bias,
              int M, int lda, int ldb, int ldc, int nChunks, int partStride)
{
    constexpr int NT = TWO ? 3 : 2;          // tiles per stage
    constexpr int STAGE = NT * TILE_B;
    extern __shared__ char smem[];
    const uint32_t sm0 = smem_u32(smem);
    const int t = threadIdx.x, lane = t & 31, w = t >> 5;
    const int wr = w & 3, wc = w >> 2;
    const int mrow0 = blockIdx.y * 128;
    const int n0 = blockIdx.x * 128;
    const int k0 = blockIdx.z * nChunks * 32;
    float* Cb = C + (size_t)blockIdx.z * partStride;

    const int row0_ = t >> 2, seg0 = t & 3;
    const int row1_ = (t + 256) >> 2, seg1 = (t + 256) & 3;
    const uint32_t so0 = (uint32_t)(row0_ * 40 + seg0 * 8) * 2;
    const uint32_t so1 = (uint32_t)(row1_ * 40 + seg1 * 8) * 2;
    const int okA0 = ((mrow0 + row0_) < M) ? 16 : 0;
    const int okA1 = ((mrow0 + row1_) < M) ? 16 : 0;
    const size_t gaBase0 = (size_t)(mrow0 + row0_) * lda + seg0 * 8 + k0;
    const size_t gaBase1 = (size_t)(mrow0 + row1_) * lda + seg1 * 8 + k0;
    const size_t gbBase0 = (size_t)(n0 + row0_) * ldb + seg0 * 8 + k0;
    const size_t gbBase1 = (size_t)(n0 + row1_) * ldb + seg1 * 8 + k0;

    const int q = lane >> 3, r8 = lane & 7;
    const uint32_t aoff = (uint32_t)((wr * 32 + r8 + ((q & 1) << 3)) * 40 + ((q >> 1) << 3)) * 2;
    const uint32_t boff = (uint32_t)((wc * 64 + r8 + ((q >> 1) << 3)) * 40 + ((q & 1) << 3)) * 2;

    float c[2][8][4];
    #pragma unroll
    for (int mt = 0; mt < 2; mt++)
        #pragma unroll
        for (int nt = 0; nt < 8; nt++)
            #pragma unroll
            for (int j = 0; j < 4; j++) c[mt][nt][j] = 0.f;

    auto stageLoad = [&](int stage, int kk) {
        uint32_t sb = sm0 + stage * STAGE;
        cpa16(sb + 0 * TILE_B + so0, Ahi + gaBase0 + kk, okA0);
        if (TWO) cpa16(sb + 1 * TILE_B + so0, Alo + gaBase0 + kk, okA0);
        cpa16(sb + (NT - 1) * TILE_B + so0, B + gbBase0 + kk, 16);
        cpa16(sb + 0 * TILE_B + so1, Ahi + gaBase1 + kk, okA1);
        if (TWO) cpa16(sb + 1 * TILE_B + so1, Alo + gaBase1 + kk, okA1);
        cpa16(sb + (NT - 1) * TILE_B + so1, B + gbBase1 + kk, 16);
        CP_COMMIT();
    };

    stageLoad(0, 0);

    for (int ch = 0; ch < nChunks; ch++) {
        const int st = ch & 1;
        const bool more = (ch + 1) < nChunks;
        if (more) stageLoad(st ^ 1, (ch + 1) * 32);
        if (more) { CP_WAIT(1); } else { CP_WAIT(0); }
        __syncthreads();

        const uint32_t base = sm0 + st * STAGE;
        #pragma unroll
        for (int ks = 0; ks < 2; ks++) {
            uint32_t ah[2][4], al2[2][4];
            #pragma unroll
            for (int mt = 0; mt < 2; mt++) {
                uint32_t aA = base + aoff + mt * (16 * 80) + ks * 32;
                ldsm4(ah[mt][0], ah[mt][1], ah[mt][2], ah[mt][3], aA);
                if (TWO) ldsm4(al2[mt][0], al2[mt][1], al2[mt][2], al2[mt][3], aA + TILE_B);
            }
            #pragma unroll
            for (int g = 0; g < 4; g++) {
                uint32_t bh[4];
                uint32_t aB = base + (NT - 1) * TILE_B + boff + g * (16 * 80) + ks * 32;
                ldsm4(bh[0], bh[1], bh[2], bh[3], aB);
                #pragma unroll
                for (int mt = 0; mt < 2; mt++) {
                    mma_f16(c[mt][2*g],   ah[mt],  &bh[0]);
                    mma_f16(c[mt][2*g+1], ah[mt],  &bh[2]);
                    if (TWO) {
                        mma_f16(c[mt][2*g],   al2[mt], &bh[0]);
                        mma_f16(c[mt][2*g+1], al2[mt], &bh[2]);
                    }
                }
            }
        }
        __syncthreads();
    }

    const int crow = mrow0 + wr * 32 + (lane >> 2);
    const int ccol = n0 + wc * 64 + (lane & 3) * 2;
    #pragma unroll
    for (int mt = 0; mt < 2; mt++) {
        #pragma unroll
        for (int nt = 0; nt < 8; nt++) {
            int col = ccol + nt * 8;
            float b0 = 0.f, b1 = 0.f;
            if (bias) { b0 = bias[col]; b1 = bias[col + 1]; }
            int r0 = crow + mt * 16;
            if (r0 < M) {
                float2 v = make_float2(c[mt][nt][0] + b0, c[mt][nt][1] + b1);
                *(float2*)(Cb + (size_t)r0 * ldc + col) = v;
            }
            int r1 = r0 + 8;
            if (r1 < M) {
                float2 v = make_float2(c[mt][nt][2] + b0, c[mt][nt][3] + b1);
                *(float2*)(Cb + (size_t)r1 * ldc + col) = v;
            }
        }
    }
}

#define GSMEM_TWO (2 * 3 * TILE_B)       // 61440
#define GSMEM_ONE (2 * 2 * TILE_B)       // 40960

// ---------------------------------------------------------------------------
// Block reduction of (sum, sumsq) over 128 threads / 4 warps.
// ---------------------------------------------------------------------------
__device__ __forceinline__ void blockReduce2_128(float& s, float& q, float* red) {
    #pragma unroll
    for (int o = 16; o > 0; o >>= 1) {
        s += __shfl_xor_sync(0xffffffffu, s, o);
        q += __shfl_xor_sync(0xffffffffu, q, o);
    }
    const int t = threadIdx.x;
    if ((t & 31) == 0) { red[t >> 5] = s; red[4 + (t >> 5)] = q; }
    __syncthreads();
    s = red[0] + red[1] + red[2] + red[3];
    q = red[4] + red[5] + red[6] + red[7];
    __syncthreads();
}

// ---------------------------------------------------------------------------
// Fused middle: 128 threads/CTA; outputs Z as single fp16
// ---------------------------------------------------------------------------
__global__ __launch_bounds__(128)
void midkernel(const float* __restrict__ x, const float* __restrict__ params,
               fp16* __restrict__ Z)
{
    __shared__ float smem[12288];
    float* sX  = smem;
    float* sM  = smem + 2048;
    float* sST = smem + 6144;
    float* sO1 = smem + 10240;
    float* red = smem;

    const int ng = blockIdx.x;
    const int t  = threadIdx.x;
    const float* xb = x + (size_t)ng * (INP * EIN);
    const float* pb = params + (size_t)(ng >> 2) * PCOLS + (size_t)(ng & 3) * TOTALP;

    {
        const float4* x4 = (const float4*)xb;
        const float4* m4 = (const float4*)pb;
        const float4* s4 = (const float4*)(pb + 4096);
        ((float4*)sX)[t]       = x4[t];
        ((float4*)sX)[t + 128] = x4[t + 128];
        ((float4*)sX)[t + 256] = x4[t + 256];
        ((float4*)sX)[t + 384] = x4[t + 384];
        #pragma unroll
        for (int i = 0; i < 8; i++)
            ((float4*)sM)[t + 128 * i] = m4[t + 128 * i];
        #pragma unroll
        for (int i = 0; i < 8; i++) {
            int idx = t + 128 * i;
            float4 v = s4[idx];
            int qq = idx >> 3;
            int p4 = (idx & 7) << 2;
            sST[(p4 + 0) * 128 + qq] = v.x;
            sST[(p4 + 1) * 128 + qq] = v.y;
            sST[(p4 + 2) * 128 + qq] = v.z;
            sST[(p4 + 3) * 128 + qq] = v.w;
        }
    }
    __syncthreads();

    const int p0 = (t >> 3) << 1;
    const int og = (t & 7) << 3;
    ull acc1[2][4];
    #pragma unroll
    for (int i = 0; i < 2; i++)
        #pragma unroll
        for (int j = 0; j < 4; j++) acc1[i][j] = 0ull;

    #pragma unroll 4
    for (int cix = 0; cix < 64; cix++) {
        float xv0 = sX[p0 * 64 + cix];
        float xv1 = sX[(p0 + 1) * 64 + cix];
        ull x0 = pack2(xv0, xv0);
        ull x1 = pack2(xv1, xv1);
        const ulonglong2* mp = (const ulonglong2*)(sM + cix * 64 + og);
        ulonglong2 m0 = mp[0], m1 = mp[1];
        fma2(acc1[0][0], x0, m0.x); fma2(acc1[0][1], x0, m0.y);
        fma2(acc1[0][2], x0, m1.x); fma2(acc1[0][3], x0, m1.y);
        fma2(acc1[1][0], x1, m0.x); fma2(acc1[1][1], x1, m0.y);
        fma2(acc1[1][2], x1, m1.x); fma2(acc1[1][3], x1, m1.y);
    }
    float v1[2][8];
    float s1 = 0.f, q1 = 0.f;
    #pragma unroll
    for (int i = 0; i < 2; i++) {
        unpack2(acc1[i][0], v1[i][0], v1[i][1]); unpack2(acc1[i][1], v1[i][2], v1[i][3]);
        unpack2(acc1[i][2], v1[i][4], v1[i][5]); unpack2(acc1[i][3], v1[i][6], v1[i][7]);
        #pragma unroll
        for (int j = 0; j < 8; j++) { s1 += v1[i][j]; q1 += v1[i][j] * v1[i][j]; }
    }
    __syncthreads();
    blockReduce2_128(s1, q1, red);
    {
        float mean = s1 * (1.f / 2048.f);
        float var  = q1 * (1.f / 2048.f) - mean * mean;
        float rs   = rsqrtf(var + 1e-5f);
        #pragma unroll
        for (int i = 0; i < 2; i++)
            #pragma unroll
            for (int j = 0; j < 8; j++)
                sO1[(p0 + i) * 64 + og + j] = fmaxf((v1[i][j] - mean) * rs, 0.f);
    }
    __syncthreads();

    const int ty = t >> 3;
    const int tx = t & 7;
    ull acc2[8][4];
    #pragma unroll
    for (int i = 0; i < 8; i++)
        #pragma unroll
        for (int j = 0; j < 4; j++) acc2[i][j] = 0ull;

    #pragma unroll 2
    for (int p = 0; p < 32; p++) {
        const float4* stp = (const float4*)(sST + p * 128 + ty * 8);
        float4 sv0 = stp[0], sv1 = stp[1];
        const ulonglong2* op = (const ulonglong2*)(sO1 + p * 64 + tx * 8);
        ulonglong2 b0 = op[0], b1 = op[1];
        float svv[8] = {sv0.x, sv0.y, sv0.z, sv0.w, sv1.x, sv1.y, sv1.z, sv1.w};
        #pragma unroll
        for (int i = 0; i < 8; i++) {
            ull sp = pack2(svv[i], svv[i]);
            fma2(acc2[i][0], sp, b0.x); fma2(acc2[i][1], sp, b0.y);
            fma2(acc2[i][2], sp, b1.x); fma2(acc2[i][3], sp, b1.y);
        }
    }
    float v2[8][8];
    float s2 = 0.f, q2 = 0.f;
    #pragma unroll
    for (int i = 0; i < 8; i++) {
        unpack2(acc2[i][0], v2[i][0], v2[i][1]); unpack2(acc2[i][1], v2[i][2], v2[i][3]);
        unpack2(acc2[i][2], v2[i][4], v2[i][5]); unpack2(acc2[i][3], v2[i][6], v2[i][7]);
        #pragma unroll
        for (int j = 0; j < 8; j++) { s2 += v2[i][j]; q2 += v2[i][j] * v2[i][j]; }
    }
    blockReduce2_128(s2, q2, red);
    float mean2 = s2 * (1.f / 8192.f);
    float var2  = q2 * (1.f / 8192.f) - mean2 * mean2;
    float rs2   = rsqrtf(var2 + 1e-5f);

    const size_t zbase = (size_t)(ng >> 2) * PCOLS + (size_t)(ng & 3) * TOTALP;
    #pragma unroll
    for (int i = 0; i < 8; i++) {
        const int qrow = ty * 8 + i;
        fp16 h[8];
        #pragma unroll
        for (int j = 0; j < 8; j++) {
            float o = fmaxf((v2[i][j] - mean2) * rs2, 0.f);
            h[j] = __float2half_rn(o);
        }
        size_t off = zbase + (size_t)qrow * 64 + tx * 8;
        *(uint4*)(Z + off) = make_uint4(hpk(h[0],h[1]), hpk(h[2],h[3]), hpk(h[4],h[5]), hpk(h[6],h[7]));
    }
}

// ---------------------------------------------------------------------------
__global__ void finalReduce(const float* __restrict__ part,
                            const float* __restrict__ query,
                            const float* __restrict__ bo,
                            float* __restrict__ out)
{
    int i = blockIdx.x * 256 + threadIdx.x;
    if (i >= NTOK * QDIM) return;
    float s = query[i] + bo[i & (QDIM - 1)];
    #pragma unroll
    for (int z = 0; z < SPLITK; z++)
        s += part[(size_t)z * NTOK * QDIM + i];
    out[i] = s;
}

// ---------------------------------------------------------------------------
extern "C" void kernel_launch(void* const* d_in, const int* in_sizes, int n_in,
                              void* d_out, int out_size)
{
    const float* x     = (const float*)d_in[0];
    const float* query = (const float*)d_in[1];
    const float* Wp    = (const float*)d_in[2];
    const float* bp    = (const float*)d_in[3];
    const float* Wo    = (const float*)d_in[4];
    const float* bo    = (const float*)d_in[5];
    float* out = (float*)d_out;

    float *pParams, *pPart;
    fp16 *pQh, *pQl, *pWpT, *pWoT, *pZ;
    cudaGetSymbolAddress((void**)&pParams, g_params);
    cudaGetSymbolAddress((void**)&pPart, g_part);
    cudaGetSymbolAddress((void**)&pQh, g_qhi);
    cudaGetSymbolAddress((void**)&pQl, g_qlo);
    cudaGetSymbolAddress((void**)&pWpT, g_wpT);
    cudaGetSymbolAddress((void**)&pWoT, g_woT);
    cudaGetSymbolAddress((void**)&pZ, g_z);

    static cudaStream_t s1 = nullptr, s2 = nullptr;
    static cudaEvent_t evRoot = nullptr, evWp = nullptr, evWo = nullptr;
    if (!s1) {
        cudaStreamCreateWithFlags(&s1, cudaStreamNonBlocking);
        cudaStreamCreateWithFlags(&s2, cudaStreamNonBlocking);
        cudaEventCreateWithFlags(&evRoot, cudaEventDisableTiming);
        cudaEventCreateWithFlags(&evWp, cudaEventDisableTiming);
        cudaEventCreateWithFlags(&evWo, cudaEventDisableTiming);
        cudaFuncSetAttribute(gemm_f16<true>,  cudaFuncAttributeMaxDynamicSharedMemorySize, GSMEM_TWO);
        cudaFuncSetAttribute(gemm_f16<false>, cudaFuncAttributeMaxDynamicSharedMemorySize, GSMEM_ONE);
    }

    cudaEventRecord(evRoot, 0);
    cudaStreamWaitEvent(s1, evRoot, 0);
    cudaStreamWaitEvent(s2, evRoot, 0);

    convQf16<<<(NTOK * QDIM / 4 + 255) / 256, 256>>>(query, pQh, pQl);
    transConvF16<<<dim3(PCOLS / 32, QDIM / 32), dim3(32, 8), 0, s1>>>(Wp, pWpT, QDIM, PCOLS);
    transConvF16<<<dim3(QDIM / 32, PCOLS / 32), dim3(32, 8), 0, s2>>>(Wo, pWoT, PCOLS, QDIM);

    cudaEventRecord(evWp, s1);
    cudaStreamWaitEvent(0, evWp, 0);

    // GEMM1: params = q @ Wp + bp   (fp16 2-pass, K=256 -> 8 chunks of 32)
    gemm_f16<true><<<dim3(PCOLS / 128, 29, 1), 256, GSMEM_TWO>>>(
        pQh, pQl, pWpT, pParams, bp, NTOK, QDIM, QDIM, PCOLS, 8, 0);

    midkernel<<<NTOK * 4, 128>>>(x, pParams, pZ);

    cudaEventRecord(evWo, s2);
    cudaStreamWaitEvent(0, evWo, 0);

    // GEMM3: part[z] = Z[:, z*1024:(z+1)*1024] @ Wo-chunk  (fp16 1-pass)
    gemm_f16<false><<<dim3(QDIM / 128, 29, SPLITK), 256, GSMEM_ONE>>>(
        pZ, nullptr, pWoT, pPart, nullptr,
        NTOK, PCOLS, PCOLS, QDIM, (PCOLS / SPLITK) / 32, (int)((size_t)NTOK * QDIM));

    finalReduce<<<(NTOK * QDIM + 255) / 256, 256>>>(pPart, query, bo, out);
}

// round 13
// speedup vs baseline: 1.7736x; 1.6075x over previous
#include <cuda_runtime.h>
#include <cuda_bf16.h>
#include <cuda_fp16.h>
#include <cstdint>

// ---------------------------------------------------------------------------
// AdaptiveMixing on GB300 (compute_103 portable path):
//   params = query @ Wp + bp   [3600 x 32768] fp16  (fp16 2-pass mma.sync)
//   per (tok,grp): x@M -> LN -> relu -> S@ -> LN -> relu -> Z  (fp32 f32x2)
//   out = Z @ Wo + bo + query  [3600 x 256]         (fp16 1-pass mma.sync)
// R12: params stored fp16 (halves GEMM1 writes + mid reads).
// Calibrated error model: each fp16 operand truncation ~2.4-2.8e-4;
// total ~5.2e-4 vs 1e-3 gate.
// ---------------------------------------------------------------------------
#define NTOK   3600
#define QDIM   256
#define PCOLS  32768
#define TOTALP 8192
#define INP    32
#define EIN    64
#define SPLITK 32

typedef unsigned long long ull;
typedef __half fp16;

// ------------------------- device scratch (no allocs) ----------------------
__device__ fp16  g_params[(size_t)NTOK * PCOLS];
__device__ fp16  g_qhi[(size_t)NTOK * QDIM];
__device__ fp16  g_qlo[(size_t)NTOK * QDIM];
__device__ fp16  g_wpT[(size_t)PCOLS * QDIM];
__device__ fp16  g_woT[(size_t)QDIM * PCOLS];
__device__ fp16  g_z[(size_t)NTOK * PCOLS];
__device__ float g_part[(size_t)SPLITK * NTOK * QDIM];

// ----------------------------- helpers -------------------------------------
__device__ __forceinline__ ull pack2(float lo, float hi) {
    ull r; asm("mov.b64 %0, {%1,%2};" : "=l"(r) : "f"(lo), "f"(hi)); return r;
}
__device__ __forceinline__ void unpack2(ull v, float& lo, float& hi) {
    asm("mov.b64 {%0,%1}, %2;" : "=f"(lo), "=f"(hi) : "l"(v));
}
__device__ __forceinline__ void fma2(ull& d, ull a, ull b) {
    asm("fma.rn.f32x2 %0, %1, %2, %0;" : "+l"(d) : "l"(a), "l"(b));
}
__device__ __forceinline__ void f2hiloH(float v, fp16& h, fp16& l) {
    h = __float2half_rn(v);
    l = __float2half_rn(v - __half2float(h));
}
__device__ __forceinline__ unsigned hpk(fp16 a, fp16 b) {
    return (unsigned)__half_as_ushort(a) | ((unsigned)__half_as_ushort(b) << 16);
}
__device__ __forceinline__ uint32_t smem_u32(const void* p) {
    uint32_t a;
    asm("{ .reg .u64 t; cvta.to.shared.u64 t, %1; cvt.u32.u64 %0, t; }" : "=r"(a) : "l"(p));
    return a;
}
__device__ __forceinline__ void ldsm4(uint32_t& r0, uint32_t& r1, uint32_t& r2, uint32_t& r3,
                                      uint32_t addr) {
    asm volatile("ldmatrix.sync.aligned.m8n8.x4.shared.b16 {%0,%1,%2,%3}, [%4];"
                 : "=r"(r0), "=r"(r1), "=r"(r2), "=r"(r3) : "r"(addr));
}
__device__ __forceinline__ void mma_f16(float* c, const uint32_t* a, const uint32_t* b) {
    asm volatile(
        "mma.sync.aligned.m16n8k16.row.col.f32.f16.f16.f32 "
        "{%0,%1,%2,%3}, {%4,%5,%6,%7}, {%8,%9}, {%0,%1,%2,%3};"
        : "+f"(c[0]), "+f"(c[1]), "+f"(c[2]), "+f"(c[3])
        : "r"(a[0]), "r"(a[1]), "r"(a[2]), "r"(a[3]), "r"(b[0]), "r"(b[1]));
}
__device__ __forceinline__ void cpa16(uint32_t dst, const void* src, int sz) {
    asm volatile("cp.async.cg.shared.global [%0], [%1], 16, %2;"
                 :: "r"(dst), "l"(src), "r"(sz) : "memory");
}
#define CP_COMMIT() asm volatile("cp.async.commit_group;" ::: "memory")
#define CP_WAIT(n)  asm volatile("cp.async.wait_group %0;" :: "n"(n) : "memory")

// ---------------------------------------------------------------------------
// Conversion kernels
// ---------------------------------------------------------------------------
__global__ void convQf16(const float* __restrict__ q, fp16* __restrict__ hi, fp16* __restrict__ lo) {
    int i = blockIdx.x * 256 + threadIdx.x;
    if (i >= NTOK * QDIM / 4) return;
    float4 v = ((const float4*)q)[i];
    fp16 h0,l0,h1,l1,h2,l2,h3,l3;
    f2hiloH(v.x,h0,l0); f2hiloH(v.y,h1,l1); f2hiloH(v.z,h2,l2); f2hiloH(v.w,h3,l3);
    ((uint2*)hi)[i] = make_uint2(hpk(h0,h1), hpk(h2,h3));
    ((uint2*)lo)[i] = make_uint2(hpk(l0,l1), hpk(l2,l3));
}

// transpose + convert to single fp16: in [R][C] f32 -> out[C][R]
__global__ void transConvF16(const float* __restrict__ in, fp16* __restrict__ o,
                             int R, int C) {
    __shared__ float tile[32][33];
    int c0 = blockIdx.x * 32, r0 = blockIdx.y * 32;
    int tx = threadIdx.x, ty = threadIdx.y;    // 32 x 8
    #pragma unroll
    for (int i = 0; i < 4; i++)
        tile[ty + 8 * i][tx] = in[(size_t)(r0 + ty + 8 * i) * C + c0 + tx];
    __syncthreads();
    #pragma unroll
    for (int i = 0; i < 4; i++) {
        float v = tile[tx][ty + 8 * i];
        o[(size_t)(c0 + ty + 8 * i) * R + r0 + tx] = __float2half_rn(v);
    }
}

// ---------------------------------------------------------------------------
// fp16 GEMM via mma.sync.
//   TWO:  A split hi/lo (2 passes) vs single A (1 pass)
//   HOUT: fp16 output (params) vs fp32 output (split-K partials)
// 128x128 CTA tile, BK=32, 8 warps (4x2), warp tile 32x64.
// smem row pitch 40 halves (80B) -> conflict-free ldmatrix.
// 2-stage cp.async, prefetch-before-wait (effective depth 2; R8-proven).
// ---------------------------------------------------------------------------
#define TILE_B   10240                   // 128 rows * 40 * 2B

template<bool TWO, bool HOUT>
__global__ __launch_bounds__(256, 2)
void gemm_f16(const fp16* __restrict__ Ahi, const fp16* __restrict__ Alo,
              const fp16* __restrict__ B,
              void* __restrict__ C, const float* __restrict__ bias,
              int M, int lda, int ldb, int ldc, int nChunks, int partStride)
{
    constexpr int NT = TWO ? 3 : 2;
    constexpr int STAGE = NT * TILE_B;
    extern __shared__ char smem[];
    const uint32_t sm0 = smem_u32(smem);
    const int t = threadIdx.x, lane = t & 31, w = t >> 5;
    const int wr = w & 3, wc = w >> 2;
    const int mrow0 = blockIdx.y * 128;
    const int n0 = blockIdx.x * 128;
    const int k0 = blockIdx.z * nChunks * 32;

    const int row0_ = t >> 2, seg0 = t & 3;
    const int row1_ = (t + 256) >> 2, seg1 = (t + 256) & 3;
    const uint32_t so0 = (uint32_t)(row0_ * 40 + seg0 * 8) * 2;
    const uint32_t so1 = (uint32_t)(row1_ * 40 + seg1 * 8) * 2;
    const int okA0 = ((mrow0 + row0_) < M) ? 16 : 0;
    const int okA1 = ((mrow0 + row1_) < M) ? 16 : 0;
    const size_t gaBase0 = (size_t)(mrow0 + row0_) * lda + seg0 * 8 + k0;
    const size_t gaBase1 = (size_t)(mrow0 + row1_) * lda + seg1 * 8 + k0;
    const size_t gbBase0 = (size_t)(n0 + row0_) * ldb + seg0 * 8 + k0;
    const size_t gbBase1 = (size_t)(n0 + row1_) * ldb + seg1 * 8 + k0;

    const int q = lane >> 3, r8 = lane & 7;
    const uint32_t aoff = (uint32_t)((wr * 32 + r8 + ((q & 1) << 3)) * 40 + ((q >> 1) << 3)) * 2;
    const uint32_t boff = (uint32_t)((wc * 64 + r8 + ((q >> 1) << 3)) * 40 + ((q & 1) << 3)) * 2;

    float c[2][8][4];
    #pragma unroll
    for (int mt = 0; mt < 2; mt++)
        #pragma unroll
        for (int nt = 0; nt < 8; nt++)
            #pragma unroll
            for (int j = 0; j < 4; j++) c[mt][nt][j] = 0.f;

    auto stageLoad = [&](int stage, int kk) {
        uint32_t sb = sm0 + stage * STAGE;
        cpa16(sb + 0 * TILE_B + so0, Ahi + gaBase0 + kk, okA0);
        if (TWO) cpa16(sb + 1 * TILE_B + so0, Alo + gaBase0 + kk, okA0);
        cpa16(sb + (NT - 1) * TILE_B + so0, B + gbBase0 + kk, 16);
        cpa16(sb + 0 * TILE_B + so1, Ahi + gaBase1 + kk, okA1);
        if (TWO) cpa16(sb + 1 * TILE_B + so1, Alo + gaBase1 + kk, okA1);
        cpa16(sb + (NT - 1) * TILE_B + so1, B + gbBase1 + kk, 16);
        CP_COMMIT();
    };

    stageLoad(0, 0);

    for (int ch = 0; ch < nChunks; ch++) {
        const int st = ch & 1;
        const bool more = (ch + 1) < nChunks;
        if (more) stageLoad(st ^ 1, (ch + 1) * 32);
        if (more) { CP_WAIT(1); } else { CP_WAIT(0); }
        __syncthreads();

        const uint32_t base = sm0 + st * STAGE;
        #pragma unroll
        for (int ks = 0; ks < 2; ks++) {
            uint32_t ah[2][4], al2[2][4];
            #pragma unroll
            for (int mt = 0; mt < 2; mt++) {
                uint32_t aA = base + aoff + mt * (16 * 80) + ks * 32;
                ldsm4(ah[mt][0], ah[mt][1], ah[mt][2], ah[mt][3], aA);
                if (TWO) ldsm4(al2[mt][0], al2[mt][1], al2[mt][2], al2[mt][3], aA + TILE_B);
            }
            #pragma unroll
            for (int g = 0; g < 4; g++) {
                uint32_t bh[4];
                uint32_t aB = base + (NT - 1) * TILE_B + boff + g * (16 * 80) + ks * 32;
                ldsm4(bh[0], bh[1], bh[2], bh[3], aB);
                #pragma unroll
                for (int mt = 0; mt < 2; mt++) {
                    mma_f16(c[mt][2*g],   ah[mt],  &bh[0]);
                    mma_f16(c[mt][2*g+1], ah[mt],  &bh[2]);
                    if (TWO) {
                        mma_f16(c[mt][2*g],   al2[mt], &bh[0]);
                        mma_f16(c[mt][2*g+1], al2[mt], &bh[2]);
                    }
                }
            }
        }
        __syncthreads();
    }

    // epilogue
    const int crow = mrow0 + wr * 32 + (lane >> 2);
    const int ccol = n0 + wc * 64 + (lane & 3) * 2;
    #pragma unroll
    for (int mt = 0; mt < 2; mt++) {
        #pragma unroll
        for (int nt = 0; nt < 8; nt++) {
            int col = ccol + nt * 8;
            float b0 = 0.f, b1 = 0.f;
            if (bias) { b0 = bias[col]; b1 = bias[col + 1]; }
            int r0 = crow + mt * 16;
            int r1 = r0 + 8;
            if (HOUT) {
                fp16* Cp = (fp16*)C + (size_t)blockIdx.z * partStride;
                if (r0 < M)
                    *(__half2*)(Cp + (size_t)r0 * ldc + col) =
                        __floats2half2_rn(c[mt][nt][0] + b0, c[mt][nt][1] + b1);
                if (r1 < M)
                    *(__half2*)(Cp + (size_t)r1 * ldc + col) =
                        __floats2half2_rn(c[mt][nt][2] + b0, c[mt][nt][3] + b1);
            } else {
                float* Cp = (float*)C + (size_t)blockIdx.z * partStride;
                if (r0 < M)
                    *(float2*)(Cp + (size_t)r0 * ldc + col) =
                        make_float2(c[mt][nt][0] + b0, c[mt][nt][1] + b1);
                if (r1 < M)
                    *(float2*)(Cp + (size_t)r1 * ldc + col) =
                        make_float2(c[mt][nt][2] + b0, c[mt][nt][3] + b1);
            }
        }
    }
}

#define GSMEM_TWO (2 * 3 * TILE_B)       // 61440
#define GSMEM_ONE (2 * 2 * TILE_B)       // 40960

// ---------------------------------------------------------------------------
// Block reduction of (sum, sumsq) over 128 threads / 4 warps.
// ---------------------------------------------------------------------------
__device__ __forceinline__ void blockReduce2_128(float& s, float& q, float* red) {
    #pragma unroll
    for (int o = 16; o > 0; o >>= 1) {
        s += __shfl_xor_sync(0xffffffffu, s, o);
        q += __shfl_xor_sync(0xffffffffu, q, o);
    }
    const int t = threadIdx.x;
    if ((t & 31) == 0) { red[t >> 5] = s; red[4 + (t >> 5)] = q; }
    __syncthreads();
    s = red[0] + red[1] + red[2] + red[3];
    q = red[4] + red[5] + red[6] + red[7];
    __syncthreads();
}

// ---------------------------------------------------------------------------
// Fused middle: 128 threads/CTA; params read as fp16, Z out as single fp16
// ---------------------------------------------------------------------------
__global__ __launch_bounds__(128)
void midkernel(const float* __restrict__ x, const fp16* __restrict__ params,
               fp16* __restrict__ Z)
{
    __shared__ float smem[12288];
    float* sX  = smem;                     // [32][64]   2048
    float* sM  = smem + 2048;              // [64][64]   4096
    float* sST = smem + 6144;              // [32][128]  4096 (S transposed)
    float* sO1 = smem + 10240;             // [32][64]   2048
    float* red = smem;

    const int ng = blockIdx.x;
    const int t  = threadIdx.x;
    const float* xb = x + (size_t)ng * (INP * EIN);
    const fp16* pb = params + (size_t)(ng >> 2) * PCOLS + (size_t)(ng & 3) * TOTALP;

    {
        const float4* x4 = (const float4*)xb;
        const uint4* m4 = (const uint4*)pb;            // 512 uint4 (4096 halves)
        const uint4* s4 = (const uint4*)(pb + 4096);   // 512 uint4
        ((float4*)sX)[t]       = x4[t];
        ((float4*)sX)[t + 128] = x4[t + 128];
        ((float4*)sX)[t + 256] = x4[t + 256];
        ((float4*)sX)[t + 384] = x4[t + 384];
        #pragma unroll
        for (int i = 0; i < 4; i++) {
            int idx = t + 128 * i;
            uint4 v = m4[idx];
            float2 f0 = __half22float2(*(__half2*)&v.x);
            float2 f1 = __half22float2(*(__half2*)&v.y);
            float2 f2 = __half22float2(*(__half2*)&v.z);
            float2 f3 = __half22float2(*(__half2*)&v.w);
            float4* d = (float4*)(sM + idx * 8);
            d[0] = make_float4(f0.x, f0.y, f1.x, f1.y);
            d[1] = make_float4(f2.x, f2.y, f3.x, f3.y);
        }
        // S: [128 q][32 p] halves -> sST[p][q] floats
        #pragma unroll
        for (int i = 0; i < 4; i++) {
            int idx = t + 128 * i;
            uint4 v = s4[idx];
            int qq = idx >> 2;             // 4 uint4 per 32-half row
            int p8 = (idx & 3) << 3;       // p base 0/8/16/24
            float2 f0 = __half22float2(*(__half2*)&v.x);
            float2 f1 = __half22float2(*(__half2*)&v.y);
            float2 f2 = __half22float2(*(__half2*)&v.z);
            float2 f3 = __half22float2(*(__half2*)&v.w);
            sST[(p8 + 0) * 128 + qq] = f0.x;
            sST[(p8 + 1) * 128 + qq] = f0.y;
            sST[(p8 + 2) * 128 + qq] = f1.x;
            sST[(p8 + 3) * 128 + qq] = f1.y;
            sST[(p8 + 4) * 128 + qq] = f2.x;
            sST[(p8 + 5) * 128 + qq] = f2.y;
            sST[(p8 + 6) * 128 + qq] = f3.x;
            sST[(p8 + 7) * 128 + qq] = f3.y;
        }
    }
    __syncthreads();

    // ---- stage 1: out1[p][o] = sum_c x[p][c]*M[c][o]; 2 rows x 8 cols ----
    const int p0 = (t >> 3) << 1;
    const int og = (t & 7) << 3;
    ull acc1[2][4];
    #pragma unroll
    for (int i = 0; i < 2; i++)
        #pragma unroll
        for (int j = 0; j < 4; j++) acc1[i][j] = 0ull;

    #pragma unroll 4
    for (int cix = 0; cix < 64; cix++) {
        float xv0 = sX[p0 * 64 + cix];
        float xv1 = sX[(p0 + 1) * 64 + cix];
        ull x0 = pack2(xv0, xv0);
        ull x1 = pack2(xv1, xv1);
        const ulonglong2* mp = (const ulonglong2*)(sM + cix * 64 + og);
        ulonglong2 m0 = mp[0], m1 = mp[1];
        fma2(acc1[0][0], x0, m0.x); fma2(acc1[0][1], x0, m0.y);
        fma2(acc1[0][2], x0, m1.x); fma2(acc1[0][3], x0, m1.y);
        fma2(acc1[1][0], x1, m0.x); fma2(acc1[1][1], x1, m0.y);
        fma2(acc1[1][2], x1, m1.x); fma2(acc1[1][3], x1, m1.y);
    }
    float v1[2][8];
    float s1 = 0.f, q1 = 0.f;
    #pragma unroll
    for (int i = 0; i < 2; i++) {
        unpack2(acc1[i][0], v1[i][0], v1[i][1]); unpack2(acc1[i][1], v1[i][2], v1[i][3]);
        unpack2(acc1[i][2], v1[i][4], v1[i][5]); unpack2(acc1[i][3], v1[i][6], v1[i][7]);
        #pragma unroll
        for (int j = 0; j < 8; j++) { s1 += v1[i][j]; q1 += v1[i][j] * v1[i][j]; }
    }
    __syncthreads();
    blockReduce2_128(s1, q1, red);
    {
        float mean = s1 * (1.f / 2048.f);
        float var  = q1 * (1.f / 2048.f) - mean * mean;
        float rs   = rsqrtf(var + 1e-5f);
        #pragma unroll
        for (int i = 0; i < 2; i++)
            #pragma unroll
            for (int j = 0; j < 8; j++)
                sO1[(p0 + i) * 64 + og + j] = fmaxf((v1[i][j] - mean) * rs, 0.f);
    }
    __syncthreads();

    // ---- stage 2: out2[q][o] = sum_p S[q][p]*out1n[p][o] ----
    const int ty = t >> 3;
    const int tx = t & 7;
    ull acc2[8][4];
    #pragma unroll
    for (int i = 0; i < 8; i++)
        #pragma unroll
        for (int j = 0; j < 4; j++) acc2[i][j] = 0ull;

    #pragma unroll 2
    for (int p = 0; p < 32; p++) {
        const float4* stp = (const float4*)(sST + p * 128 + ty * 8);
        float4 sv0 = stp[0], sv1 = stp[1];
        const ulonglong2* op = (const ulonglong2*)(sO1 + p * 64 + tx * 8);
        ulonglong2 b0 = op[0], b1 = op[1];
        float svv[8] = {sv0.x, sv0.y, sv0.z, sv0.w, sv1.x, sv1.y, sv1.z, sv1.w};
        #pragma unroll
        for (int i = 0; i < 8; i++) {
            ull sp = pack2(svv[i], svv[i]);
            fma2(acc2[i][0], sp, b0.x); fma2(acc2[i][1], sp, b0.y);
            fma2(acc2[i][2], sp, b1.x); fma2(acc2[i][3], sp, b1.y);
        }
    }
    float v2[8][8];
    float s2 = 0.f, q2 = 0.f;
    #pragma unroll
    for (int i = 0; i < 8; i++) {
        unpack2(acc2[i][0], v2[i][0], v2[i][1]); unpack2(acc2[i][1], v2[i][2], v2[i][3]);
        unpack2(acc2[i][2], v2[i][4], v2[i][5]); unpack2(acc2[i][3], v2[i][6], v2[i][7]);
        #pragma unroll
        for (int j = 0; j < 8; j++) { s2 += v2[i][j]; q2 += v2[i][j] * v2[i][j]; }
    }
    blockReduce2_128(s2, q2, red);
    float mean2 = s2 * (1.f / 8192.f);
    float var2  = q2 * (1.f / 8192.f) - mean2 * mean2;
    float rs2   = rsqrtf(var2 + 1e-5f);

    const size_t zbase = (size_t)(ng >> 2) * PCOLS + (size_t)(ng & 3) * TOTALP;
    #pragma unroll
    for (int i = 0; i < 8; i++) {
        const int qrow = ty * 8 + i;
        fp16 h[8];
        #pragma unroll
        for (int j = 0; j < 8; j++) {
            float o = fmaxf((v2[i][j] - mean2) * rs2, 0.f);
            h[j] = __float2half_rn(o);
        }
        size_t off = zbase + (size_t)qrow * 64 + tx * 8;
        *(uint4*)(Z + off) = make_uint4(hpk(h[0],h[1]), hpk(h[2],h[3]), hpk(h[4],h[5]), hpk(h[6],h[7]));
    }
}

// ---------------------------------------------------------------------------
__global__ void finalReduce(const float* __restrict__ part,
                            const float* __restrict__ query,
                            const float* __restrict__ bo,
                            float* __restrict__ out)
{
    int i = blockIdx.x * 256 + threadIdx.x;
    if (i >= NTOK * QDIM) return;
    float s = query[i] + bo[i & (QDIM - 1)];
    #pragma unroll
    for (int z = 0; z < SPLITK; z++)
        s += part[(size_t)z * NTOK * QDIM + i];
    out[i] = s;
}

// ---------------------------------------------------------------------------
extern "C" void kernel_launch(void* const* d_in, const int* in_sizes, int n_in,
                              void* d_out, int out_size)
{
    const float* x     = (const float*)d_in[0];
    const float* query = (const float*)d_in[1];
    const float* Wp    = (const float*)d_in[2];
    const float* bp    = (const float*)d_in[3];
    const float* Wo    = (const float*)d_in[4];
    const float* bo    = (const float*)d_in[5];
    float* out = (float*)d_out;

    float* pPart;
    fp16 *pParams, *pQh, *pQl, *pWpT, *pWoT, *pZ;
    cudaGetSymbolAddress((void**)&pParams, g_params);
    cudaGetSymbolAddress((void**)&pPart, g_part);
    cudaGetSymbolAddress((void**)&pQh, g_qhi);
    cudaGetSymbolAddress((void**)&pQl, g_qlo);
    cudaGetSymbolAddress((void**)&pWpT, g_wpT);
    cudaGetSymbolAddress((void**)&pWoT, g_woT);
    cudaGetSymbolAddress((void**)&pZ, g_z);

    static cudaStream_t s1 = nullptr, s2 = nullptr;
    static cudaEvent_t evRoot = nullptr, evWp = nullptr, evWo = nullptr;
    if (!s1) {
        cudaStreamCreateWithFlags(&s1, cudaStreamNonBlocking);
        cudaStreamCreateWithFlags(&s2, cudaStreamNonBlocking);
        cudaEventCreateWithFlags(&evRoot, cudaEventDisableTiming);
        cudaEventCreateWithFlags(&evWp, cudaEventDisableTiming);
        cudaEventCreateWithFlags(&evWo, cudaEventDisableTiming);
        cudaFuncSetAttribute((const void*)gemm_f16<true, true>,
                             cudaFuncAttributeMaxDynamicSharedMemorySize, GSMEM_TWO);
        cudaFuncSetAttribute((const void*)gemm_f16<false, false>,
                             cudaFuncAttributeMaxDynamicSharedMemorySize, GSMEM_ONE);
    }

    cudaEventRecord(evRoot, 0);
    cudaStreamWaitEvent(s1, evRoot, 0);
    cudaStreamWaitEvent(s2, evRoot, 0);

    convQf16<<<(NTOK * QDIM / 4 + 255) / 256, 256>>>(query, pQh, pQl);
    transConvF16<<<dim3(PCOLS / 32, QDIM / 32), dim3(32, 8), 0, s1>>>(Wp, pWpT, QDIM, PCOLS);
    transConvF16<<<dim3(QDIM / 32, PCOLS / 32), dim3(32, 8), 0, s2>>>(Wo, pWoT, PCOLS, QDIM);

    cudaEventRecord(evWp, s1);
    cudaStreamWaitEvent(0, evWp, 0);

    // GEMM1: params(fp16) = q @ Wp + bp  (fp16 2-pass, K=256 -> 8 chunks)
    gemm_f16<true, true><<<dim3(PCOLS / 128, 29, 1), 256, GSMEM_TWO>>>(
        pQh, pQl, pWpT, pParams, bp, NTOK, QDIM, QDIM, PCOLS, 8, 0);

    midkernel<<<NTOK * 4, 128>>>(x, pParams, pZ);

    cudaEventRecord(evWo, s2);
    cudaStreamWaitEvent(0, evWo, 0);

    // GEMM3: part[z] = Z[:, z*1024:(z+1)*1024] @ Wo-chunk  (fp16 1-pass)
    gemm_f16<false, false><<<dim3(QDIM / 128, 29, SPLITK), 256, GSMEM_ONE>>>(
        pZ, nullptr, pWoT, pPart, nullptr,
        NTOK, PCOLS, PCOLS, QDIM, (PCOLS / SPLITK) / 32, (int)((size_t)NTOK * QDIM));

    finalReduce<<<(NTOK * QDIM + 255) / 256, 256>>>(pPart, query, bo, out);
}

// round 14
// speedup vs baseline: 2.0088x; 1.1327x over previous
#include <cuda_runtime.h>
#include <cuda_bf16.h>
#include <cuda_fp16.h>
#include <cstdint>

// ---------------------------------------------------------------------------
// AdaptiveMixing on GB300 (compute_103 portable path):
//   params = query @ Wp + bp   [3600 x 32768] fp16  (fp16 1-pass mma.sync)
//   per (tok,grp): x@M -> LN -> relu -> S@ -> LN -> relu -> Z  (fp32 f32x2)
//   out = Z @ Wo + bo + query  [3600 x 256]         (fp16 1-pass mma.sync)
// R14: GEMM1 single-pass (query single fp16). All GEMM operands single fp16.
// Calibrated quadrature error model: ~2.4-2.8e-4 per fp16 truncation;
// total ~5.5e-4 vs 1e-3 gate.
// ---------------------------------------------------------------------------
#define NTOK   3600
#define QDIM   256
#define PCOLS  32768
#define TOTALP 8192
#define INP    32
#define EIN    64
#define SPLITK 32

typedef unsigned long long ull;
typedef __half fp16;

// ------------------------- device scratch (no allocs) ----------------------
__device__ fp16  g_params[(size_t)NTOK * PCOLS];
__device__ fp16  g_q16[(size_t)NTOK * QDIM];
__device__ fp16  g_wpT[(size_t)PCOLS * QDIM];
__device__ fp16  g_woT[(size_t)QDIM * PCOLS];
__device__ fp16  g_z[(size_t)NTOK * PCOLS];
__device__ float g_part[(size_t)SPLITK * NTOK * QDIM];

// ----------------------------- helpers -------------------------------------
__device__ __forceinline__ ull pack2(float lo, float hi) {
    ull r; asm("mov.b64 %0, {%1,%2};" : "=l"(r) : "f"(lo), "f"(hi)); return r;
}
__device__ __forceinline__ void unpack2(ull v, float& lo, float& hi) {
    asm("mov.b64 {%0,%1}, %2;" : "=f"(lo), "=f"(hi) : "l"(v));
}
__device__ __forceinline__ void fma2(ull& d, ull a, ull b) {
    asm("fma.rn.f32x2 %0, %1, %2, %0;" : "+l"(d) : "l"(a), "l"(b));
}
__device__ __forceinline__ unsigned hpk(fp16 a, fp16 b) {
    return (unsigned)__half_as_ushort(a) | ((unsigned)__half_as_ushort(b) << 16);
}
__device__ __forceinline__ uint32_t smem_u32(const void* p) {
    uint32_t a;
    asm("{ .reg .u64 t; cvta.to.shared.u64 t, %1; cvt.u32.u64 %0, t; }" : "=r"(a) : "l"(p));
    return a;
}
__device__ __forceinline__ void ldsm4(uint32_t& r0, uint32_t& r1, uint32_t& r2, uint32_t& r3,
                                      uint32_t addr) {
    asm volatile("ldmatrix.sync.aligned.m8n8.x4.shared.b16 {%0,%1,%2,%3}, [%4];"
                 : "=r"(r0), "=r"(r1), "=r"(r2), "=r"(r3) : "r"(addr));
}
__device__ __forceinline__ void mma_f16(float* c, const uint32_t* a, const uint32_t* b) {
    asm volatile(
        "mma.sync.aligned.m16n8k16.row.col.f32.f16.f16.f32 "
        "{%0,%1,%2,%3}, {%4,%5,%6,%7}, {%8,%9}, {%0,%1,%2,%3};"
        : "+f"(c[0]), "+f"(c[1]), "+f"(c[2]), "+f"(c[3])
        : "r"(a[0]), "r"(a[1]), "r"(a[2]), "r"(a[3]), "r"(b[0]), "r"(b[1]));
}
__device__ __forceinline__ void cpa16(uint32_t dst, const void* src, int sz) {
    asm volatile("cp.async.cg.shared.global [%0], [%1], 16, %2;"
                 :: "r"(dst), "l"(src), "r"(sz) : "memory");
}
#define CP_COMMIT() asm volatile("cp.async.commit_group;" ::: "memory")
#define CP_WAIT(n)  asm volatile("cp.async.wait_group %0;" :: "n"(n) : "memory")

// ---------------------------------------------------------------------------
// Conversion kernels
// ---------------------------------------------------------------------------
__global__ void convQf16(const float* __restrict__ q, fp16* __restrict__ o) {
    int i = blockIdx.x * 256 + threadIdx.x;
    if (i >= NTOK * QDIM / 4) return;
    float4 v = ((const float4*)q)[i];
    ((uint2*)o)[i] = make_uint2(
        hpk(__float2half_rn(v.x), __float2half_rn(v.y)),
        hpk(__float2half_rn(v.z), __float2half_rn(v.w)));
}

// transpose + convert to single fp16: in [R][C] f32 -> out [C][R]
__global__ void transConvF16(const float* __restrict__ in, fp16* __restrict__ o,
                             int R, int C) {
    __shared__ float tile[32][33];
    int c0 = blockIdx.x * 32, r0 = blockIdx.y * 32;
    int tx = threadIdx.x, ty = threadIdx.y;    // 32 x 8
    #pragma unroll
    for (int i = 0; i < 4; i++)
        tile[ty + 8 * i][tx] = in[(size_t)(r0 + ty + 8 * i) * C + c0 + tx];
    __syncthreads();
    #pragma unroll
    for (int i = 0; i < 4; i++) {
        float v = tile[tx][ty + 8 * i];
        o[(size_t)(c0 + ty + 8 * i) * R + r0 + tx] = __float2half_rn(v);
    }
}

// ---------------------------------------------------------------------------
// fp16 single-pass GEMM via mma.sync.   HOUT: fp16 vs fp32 output.
// 128x128 CTA tile, BK=32, 8 warps (4x2), warp tile 32x64.
// smem row pitch 40 halves (80B) -> conflict-free ldmatrix.
// 2-stage cp.async, prefetch-before-wait (effective depth 2; R8-proven).
// ---------------------------------------------------------------------------
#define TILE_B   10240                   // 128 rows * 40 * 2B
#define STAGE_B  (2 * TILE_B)            // A, B
#define GSMEM1   (2 * STAGE_B)           // 40960

template<bool HOUT>
__global__ __launch_bounds__(256, 2)
void gemm_f16(const fp16* __restrict__ A, const fp16* __restrict__ B,
              void* __restrict__ C, const float* __restrict__ bias,
              int M, int lda, int ldb, int ldc, int nChunks, int partStride)
{
    extern __shared__ char smem[];
    const uint32_t sm0 = smem_u32(smem);
    const int t = threadIdx.x, lane = t & 31, w = t >> 5;
    const int wr = w & 3, wc = w >> 2;
    const int mrow0 = blockIdx.y * 128;
    const int n0 = blockIdx.x * 128;
    const int k0 = blockIdx.z * nChunks * 32;

    const int row0_ = t >> 2, seg0 = t & 3;
    const int row1_ = (t + 256) >> 2, seg1 = (t + 256) & 3;
    const uint32_t so0 = (uint32_t)(row0_ * 40 + seg0 * 8) * 2;
    const uint32_t so1 = (uint32_t)(row1_ * 40 + seg1 * 8) * 2;
    const int okA0 = ((mrow0 + row0_) < M) ? 16 : 0;
    const int okA1 = ((mrow0 + row1_) < M) ? 16 : 0;
    const size_t gaBase0 = (size_t)(mrow0 + row0_) * lda + seg0 * 8 + k0;
    const size_t gaBase1 = (size_t)(mrow0 + row1_) * lda + seg1 * 8 + k0;
    const size_t gbBase0 = (size_t)(n0 + row0_) * ldb + seg0 * 8 + k0;
    const size_t gbBase1 = (size_t)(n0 + row1_) * ldb + seg1 * 8 + k0;

    const int q = lane >> 3, r8 = lane & 7;
    const uint32_t aoff = (uint32_t)((wr * 32 + r8 + ((q & 1) << 3)) * 40 + ((q >> 1) << 3)) * 2;
    const uint32_t boff = (uint32_t)((wc * 64 + r8 + ((q >> 1) << 3)) * 40 + ((q & 1) << 3)) * 2;

    float c[2][8][4];
    #pragma unroll
    for (int mt = 0; mt < 2; mt++)
        #pragma unroll
        for (int nt = 0; nt < 8; nt++)
            #pragma unroll
            for (int j = 0; j < 4; j++) c[mt][nt][j] = 0.f;

    auto stageLoad = [&](int stage, int kk) {
        uint32_t sb = sm0 + stage * STAGE_B;
        cpa16(sb + 0 * TILE_B + so0, A + gaBase0 + kk, okA0);
        cpa16(sb + 1 * TILE_B + so0, B + gbBase0 + kk, 16);
        cpa16(sb + 0 * TILE_B + so1, A + gaBase1 + kk, okA1);
        cpa16(sb + 1 * TILE_B + so1, B + gbBase1 + kk, 16);
        CP_COMMIT();
    };

    stageLoad(0, 0);

    for (int ch = 0; ch < nChunks; ch++) {
        const int st = ch & 1;
        const bool more = (ch + 1) < nChunks;
        if (more) stageLoad(st ^ 1, (ch + 1) * 32);
        if (more) { CP_WAIT(1); } else { CP_WAIT(0); }
        __syncthreads();

        const uint32_t base = sm0 + st * STAGE_B;
        #pragma unroll
        for (int ks = 0; ks < 2; ks++) {
            uint32_t ah[2][4];
            #pragma unroll
            for (int mt = 0; mt < 2; mt++) {
                uint32_t aA = base + aoff + mt * (16 * 80) + ks * 32;
                ldsm4(ah[mt][0], ah[mt][1], ah[mt][2], ah[mt][3], aA);
            }
            #pragma unroll
            for (int g = 0; g < 4; g++) {
                uint32_t bh[4];
                uint32_t aB = base + TILE_B + boff + g * (16 * 80) + ks * 32;
                ldsm4(bh[0], bh[1], bh[2], bh[3], aB);
                #pragma unroll
                for (int mt = 0; mt < 2; mt++) {
                    mma_f16(c[mt][2*g],   ah[mt], &bh[0]);
                    mma_f16(c[mt][2*g+1], ah[mt], &bh[2]);
                }
            }
        }
        __syncthreads();
    }

    // epilogue
    const int crow = mrow0 + wr * 32 + (lane >> 2);
    const int ccol = n0 + wc * 64 + (lane & 3) * 2;
    #pragma unroll
    for (int mt = 0; mt < 2; mt++) {
        #pragma unroll
        for (int nt = 0; nt < 8; nt++) {
            int col = ccol + nt * 8;
            float b0 = 0.f, b1 = 0.f;
            if (bias) { b0 = bias[col]; b1 = bias[col + 1]; }
            int r0 = crow + mt * 16;
            int r1 = r0 + 8;
            if (HOUT) {
                fp16* Cp = (fp16*)C + (size_t)blockIdx.z * partStride;
                if (r0 < M)
                    *(__half2*)(Cp + (size_t)r0 * ldc + col) =
                        __floats2half2_rn(c[mt][nt][0] + b0, c[mt][nt][1] + b1);
                if (r1 < M)
                    *(__half2*)(Cp + (size_t)r1 * ldc + col) =
                        __floats2half2_rn(c[mt][nt][2] + b0, c[mt][nt][3] + b1);
            } else {
                float* Cp = (float*)C + (size_t)blockIdx.z * partStride;
                if (r0 < M)
                    *(float2*)(Cp + (size_t)r0 * ldc + col) =
                        make_float2(c[mt][nt][0] + b0, c[mt][nt][1] + b1);
                if (r1 < M)
                    *(float2*)(Cp + (size_t)r1 * ldc + col) =
                        make_float2(c[mt][nt][2] + b0, c[mt][nt][3] + b1);
            }
        }
    }
}

// ---------------------------------------------------------------------------
// Block reduction of (sum, sumsq) over 128 threads / 4 warps.
// ---------------------------------------------------------------------------
__device__ __forceinline__ void blockReduce2_128(float& s, float& q, float* red) {
    #pragma unroll
    for (int o = 16; o > 0; o >>= 1) {
        s += __shfl_xor_sync(0xffffffffu, s, o);
        q += __shfl_xor_sync(0xffffffffu, q, o);
    }
    const int t = threadIdx.x;
    if ((t & 31) == 0) { red[t >> 5] = s; red[4 + (t >> 5)] = q; }
    __syncthreads();
    s = red[0] + red[1] + red[2] + red[3];
    q = red[4] + red[5] + red[6] + red[7];
    __syncthreads();
}

// ---------------------------------------------------------------------------
// Fused middle: 128 threads/CTA; params read as fp16, Z out as single fp16
// ---------------------------------------------------------------------------
__global__ __launch_bounds__(128)
void midkernel(const float* __restrict__ x, const fp16* __restrict__ params,
               fp16* __restrict__ Z)
{
    __shared__ float smem[12288];
    float* sX  = smem;                     // [32][64]   2048
    float* sM  = smem + 2048;              // [64][64]   4096
    float* sST = smem + 6144;              // [32][128]  4096 (S transposed)
    float* sO1 = smem + 10240;             // [32][64]   2048
    float* red = smem;

    const int ng = blockIdx.x;
    const int t  = threadIdx.x;
    const float* xb = x + (size_t)ng * (INP * EIN);
    const fp16* pb = params + (size_t)(ng >> 2) * PCOLS + (size_t)(ng & 3) * TOTALP;

    {
        const float4* x4 = (const float4*)xb;
        const uint4* m4 = (const uint4*)pb;            // 512 uint4 (4096 halves)
        const uint4* s4 = (const uint4*)(pb + 4096);   // 512 uint4
        ((float4*)sX)[t]       = x4[t];
        ((float4*)sX)[t + 128] = x4[t + 128];
        ((float4*)sX)[t + 256] = x4[t + 256];
        ((float4*)sX)[t + 384] = x4[t + 384];
        #pragma unroll
        for (int i = 0; i < 4; i++) {
            int idx = t + 128 * i;
            uint4 v = m4[idx];
            float2 f0 = __half22float2(*(__half2*)&v.x);
            float2 f1 = __half22float2(*(__half2*)&v.y);
            float2 f2 = __half22float2(*(__half2*)&v.z);
            float2 f3 = __half22float2(*(__half2*)&v.w);
            float4* d = (float4*)(sM + idx * 8);
            d[0] = make_float4(f0.x, f0.y, f1.x, f1.y);
            d[1] = make_float4(f2.x, f2.y, f3.x, f3.y);
        }
        // S: [128 q][32 p] halves -> sST[p][q] floats
        #pragma unroll
        for (int i = 0; i < 4; i++) {
            int idx = t + 128 * i;
            uint4 v = s4[idx];
            int qq = idx >> 2;             // 4 uint4 per 32-half row
            int p8 = (idx & 3) << 3;
            float2 f0 = __half22float2(*(__half2*)&v.x);
            float2 f1 = __half22float2(*(__half2*)&v.y);
            float2 f2 = __half22float2(*(__half2*)&v.z);
            float2 f3 = __half22float2(*(__half2*)&v.w);
            sST[(p8 + 0) * 128 + qq] = f0.x;
            sST[(p8 + 1) * 128 + qq] = f0.y;
            sST[(p8 + 2) * 128 + qq] = f1.x;
            sST[(p8 + 3) * 128 + qq] = f1.y;
            sST[(p8 + 4) * 128 + qq] = f2.x;
            sST[(p8 + 5) * 128 + qq] = f2.y;
            sST[(p8 + 6) * 128 + qq] = f3.x;
            sST[(p8 + 7) * 128 + qq] = f3.y;
        }
    }
    __syncthreads();

    // ---- stage 1: out1[p][o] = sum_c x[p][c]*M[c][o]; 2 rows x 8 cols ----
    const int p0 = (t >> 3) << 1;
    const int og = (t & 7) << 3;
    ull acc1[2][4];
    #pragma unroll
    for (int i = 0; i < 2; i++)
        #pragma unroll
        for (int j = 0; j < 4; j++) acc1[i][j] = 0ull;

    #pragma unroll 4
    for (int cix = 0; cix < 64; cix++) {
        float xv0 = sX[p0 * 64 + cix];
        float xv1 = sX[(p0 + 1) * 64 + cix];
        ull x0 = pack2(xv0, xv0);
        ull x1 = pack2(xv1, xv1);
        const ulonglong2* mp = (const ulonglong2*)(sM + cix * 64 + og);
        ulonglong2 m0 = mp[0], m1 = mp[1];
        fma2(acc1[0][0], x0, m0.x); fma2(acc1[0][1], x0, m0.y);
        fma2(acc1[0][2], x0, m1.x); fma2(acc1[0][3], x0, m1.y);
        fma2(acc1[1][0], x1, m0.x); fma2(acc1[1][1], x1, m0.y);
        fma2(acc1[1][2], x1, m1.x); fma2(acc1[1][3], x1, m1.y);
    }
    float v1[2][8];
    float s1 = 0.f, q1 = 0.f;
    #pragma unroll
    for (int i = 0; i < 2; i++) {
        unpack2(acc1[i][0], v1[i][0], v1[i][1]); unpack2(acc1[i][1], v1[i][2], v1[i][3]);
        unpack2(acc1[i][2], v1[i][4], v1[i][5]); unpack2(acc1[i][3], v1[i][6], v1[i][7]);
        #pragma unroll
        for (int j = 0; j < 8; j++) { s1 += v1[i][j]; q1 += v1[i][j] * v1[i][j]; }
    }
    __syncthreads();
    blockReduce2_128(s1, q1, red);
    {
        float mean = s1 * (1.f / 2048.f);
        float var  = q1 * (1.f / 2048.f) - mean * mean;
        float rs   = rsqrtf(var + 1e-5f);
        #pragma unroll
        for (int i = 0; i < 2; i++)
            #pragma unroll
            for (int j = 0; j < 8; j++)
                sO1[(p0 + i) * 64 + og + j] = fmaxf((v1[i][j] - mean) * rs, 0.f);
    }
    __syncthreads();

    // ---- stage 2: out2[q][o] = sum_p S[q][p]*out1n[p][o] ----
    const int ty = t >> 3;
    const int tx = t & 7;
    ull acc2[8][4];
    #pragma unroll
    for (int i = 0; i < 8; i++)
        #pragma unroll
        for (int j = 0; j < 4; j++) acc2[i][j] = 0ull;

    #pragma unroll 2
    for (int p = 0; p < 32; p++) {
        const float4* stp = (const float4*)(sST + p * 128 + ty * 8);
        float4 sv0 = stp[0], sv1 = stp[1];
        const ulonglong2* op = (const ulonglong2*)(sO1 + p * 64 + tx * 8);
        ulonglong2 b0 = op[0], b1 = op[1];
        float svv[8] = {sv0.x, sv0.y, sv0.z, sv0.w, sv1.x, sv1.y, sv1.z, sv1.w};
        #pragma unroll
        for (int i = 0; i < 8; i++) {
            ull sp = pack2(svv[i], svv[i]);
            fma2(acc2[i][0], sp, b0.x); fma2(acc2[i][1], sp, b0.y);
            fma2(acc2[i][2], sp, b1.x); fma2(acc2[i][3], sp, b1.y);
        }
    }
    float v2[8][8];
    float s2 = 0.f, q2 = 0.f;
    #pragma unroll
    for (int i = 0; i < 8; i++) {
        unpack2(acc2[i][0], v2[i][0], v2[i][1]); unpack2(acc2[i][1], v2[i][2], v2[i][3]);
        unpack2(acc2[i][2], v2[i][4], v2[i][5]); unpack2(acc2[i][3], v2[i][6], v2[i][7]);
        #pragma unroll
        for (int j = 0; j < 8; j++) { s2 += v2[i][j]; q2 += v2[i][j] * v2[i][j]; }
    }
    blockReduce2_128(s2, q2, red);
    float mean2 = s2 * (1.f / 8192.f);
    float var2  = q2 * (1.f / 8192.f) - mean2 * mean2;
    float rs2   = rsqrtf(var2 + 1e-5f);

    const size_t zbase = (size_t)(ng >> 2) * PCOLS + (size_t)(ng & 3) * TOTALP;
    #pragma unroll
    for (int i = 0; i < 8; i++) {
        const int qrow = ty * 8 + i;
        fp16 h[8];
        #pragma unroll
        for (int j = 0; j < 8; j++) {
            float o = fmaxf((v2[i][j] - mean2) * rs2, 0.f);
            h[j] = __float2half_rn(o);
        }
        size_t off = zbase + (size_t)qrow * 64 + tx * 8;
        *(uint4*)(Z + off) = make_uint4(hpk(h[0],h[1]), hpk(h[2],h[3]), hpk(h[4],h[5]), hpk(h[6],h[7]));
    }
}

// ---------------------------------------------------------------------------
__global__ void finalReduce(const float* __restrict__ part,
                            const float* __restrict__ query,
                            const float* __restrict__ bo,
                            float* __restrict__ out)
{
    int i = blockIdx.x * 256 + threadIdx.x;
    if (i >= NTOK * QDIM) return;
    float s = query[i] + bo[i & (QDIM - 1)];
    #pragma unroll
    for (int z = 0; z < SPLITK; z++)
        s += part[(size_t)z * NTOK * QDIM + i];
    out[i] = s;
}

// ---------------------------------------------------------------------------
extern "C" void kernel_launch(void* const* d_in, const int* in_sizes, int n_in,
                              void* d_out, int out_size)
{
    const float* x     = (const float*)d_in[0];
    const float* query = (const float*)d_in[1];
    const float* Wp    = (const float*)d_in[2];
    const float* bp    = (const float*)d_in[3];
    const float* Wo    = (const float*)d_in[4];
    const float* bo    = (const float*)d_in[5];
    float* out = (float*)d_out;

    float* pPart;
    fp16 *pParams, *pQ, *pWpT, *pWoT, *pZ;
    cudaGetSymbolAddress((void**)&pParams, g_params);
    cudaGetSymbolAddress((void**)&pPart, g_part);
    cudaGetSymbolAddress((void**)&pQ, g_q16);
    cudaGetSymbolAddress((void**)&pWpT, g_wpT);
    cudaGetSymbolAddress((void**)&pWoT, g_woT);
    cudaGetSymbolAddress((void**)&pZ, g_z);

    static cudaStream_t s1 = nullptr, s2 = nullptr;
    static cudaEvent_t evRoot = nullptr, evWp = nullptr, evWo = nullptr;
    if (!s1) {
        cudaStreamCreateWithFlags(&s1, cudaStreamNonBlocking);
        cudaStreamCreateWithFlags(&s2, cudaStreamNonBlocking);
        cudaEventCreateWithFlags(&evRoot, cudaEventDisableTiming);
        cudaEventCreateWithFlags(&evWp, cudaEventDisableTiming);
        cudaEventCreateWithFlags(&evWo, cudaEventDisableTiming);
        cudaFuncSetAttribute((const void*)gemm_f16<true>,
                             cudaFuncAttributeMaxDynamicSharedMemorySize, GSMEM1);
        cudaFuncSetAttribute((const void*)gemm_f16<false>,
                             cudaFuncAttributeMaxDynamicSharedMemorySize, GSMEM1);
    }

    cudaEventRecord(evRoot, 0);
    cudaStreamWaitEvent(s1, evRoot, 0);
    cudaStreamWaitEvent(s2, evRoot, 0);

    convQf16<<<(NTOK * QDIM / 4 + 255) / 256, 256>>>(query, pQ);
    transConvF16<<<dim3(PCOLS / 32, QDIM / 32), dim3(32, 8), 0, s1>>>(Wp, pWpT, QDIM, PCOLS);
    transConvF16<<<dim3(QDIM / 32, PCOLS / 32), dim3(32, 8), 0, s2>>>(Wo, pWoT, PCOLS, QDIM);

    cudaEventRecord(evWp, s1);
    cudaStreamWaitEvent(0, evWp, 0);

    // GEMM1: params(fp16) = q @ Wp + bp  (fp16 1-pass, K=256 -> 8 chunks)
    gemm_f16<true><<<dim3(PCOLS / 128, 29, 1), 256, GSMEM1>>>(
        pQ, pWpT, pParams, bp, NTOK, QDIM, QDIM, PCOLS, 8, 0);

    midkernel<<<NTOK * 4, 128>>>(x, pParams, pZ);

    cudaEventRecord(evWo, s2);
    cudaStreamWaitEvent(0, evWo, 0);

    // GEMM3: part[z] = Z[:, z*1024:(z+1)*1024] @ Wo-chunk  (fp16 1-pass)
    gemm_f16<false><<<dim3(QDIM / 128, 29, SPLITK), 256, GSMEM1>>>(
        pZ, pWoT, pPart, nullptr,
        NTOK, PCOLS, PCOLS, QDIM, (PCOLS / SPLITK) / 32, (int)((size_t)NTOK * QDIM));

    finalReduce<<<(NTOK * QDIM + 255) / 256, 256>>>(pPart, query, bo, out);
}

// round 15
// speedup vs baseline: 2.1365x; 1.0635x over previous
#include <cuda_runtime.h>
#include <cuda_bf16.h>
#include <cuda_fp16.h>
#include <cstdint>

// ---------------------------------------------------------------------------
// AdaptiveMixing on GB300 (compute_103 portable path):
//   params = query @ Wp + bp   [3600 x 32768] fp16  (fp16 1-pass mma.sync)
//   per (tok,grp): x@M -> LN -> relu (scalar f32x2)
//                  -> S@out1 via mma.sync fp16 -> LN -> relu -> Z
//   out = Z @ Wo + bo + query  [3600 x 256]         (fp16 1-pass mma.sync)
// R15: mid stage-2 on tensor cores (S already fp16; out1 truncated fp16).
// Calibrated quadrature error model: ~2.4-2.8e-4 per fp16 truncation;
// predicted total ~6.2e-4 vs 1e-3 gate.
// ---------------------------------------------------------------------------
#define NTOK   3600
#define QDIM   256
#define PCOLS  32768
#define TOTALP 8192
#define INP    32
#define EIN    64
#define SPLITK 32

typedef unsigned long long ull;
typedef __half fp16;

// ------------------------- device scratch (no allocs) ----------------------
__device__ fp16  g_params[(size_t)NTOK * PCOLS];
__device__ fp16  g_q16[(size_t)NTOK * QDIM];
__device__ fp16  g_wpT[(size_t)PCOLS * QDIM];
__device__ fp16  g_woT[(size_t)QDIM * PCOLS];
__device__ fp16  g_z[(size_t)NTOK * PCOLS];
__device__ float g_part[(size_t)SPLITK * NTOK * QDIM];

// ----------------------------- helpers -------------------------------------
__device__ __forceinline__ ull pack2(float lo, float hi) {
    ull r; asm("mov.b64 %0, {%1,%2};" : "=l"(r) : "f"(lo), "f"(hi)); return r;
}
__device__ __forceinline__ void unpack2(ull v, float& lo, float& hi) {
    asm("mov.b64 {%0,%1}, %2;" : "=f"(lo), "=f"(hi) : "l"(v));
}
__device__ __forceinline__ void fma2(ull& d, ull a, ull b) {
    asm("fma.rn.f32x2 %0, %1, %2, %0;" : "+l"(d) : "l"(a), "l"(b));
}
__device__ __forceinline__ unsigned hpk(fp16 a, fp16 b) {
    return (unsigned)__half_as_ushort(a) | ((unsigned)__half_as_ushort(b) << 16);
}
__device__ __forceinline__ uint32_t smem_u32(const void* p) {
    uint32_t a;
    asm("{ .reg .u64 t; cvta.to.shared.u64 t, %1; cvt.u32.u64 %0, t; }" : "=r"(a) : "l"(p));
    return a;
}
__device__ __forceinline__ void ldsm4(uint32_t& r0, uint32_t& r1, uint32_t& r2, uint32_t& r3,
                                      uint32_t addr) {
    asm volatile("ldmatrix.sync.aligned.m8n8.x4.shared.b16 {%0,%1,%2,%3}, [%4];"
                 : "=r"(r0), "=r"(r1), "=r"(r2), "=r"(r3) : "r"(addr));
}
__device__ __forceinline__ void mma_f16(float* c, const uint32_t* a, const uint32_t* b) {
    asm volatile(
        "mma.sync.aligned.m16n8k16.row.col.f32.f16.f16.f32 "
        "{%0,%1,%2,%3}, {%4,%5,%6,%7}, {%8,%9}, {%0,%1,%2,%3};"
        : "+f"(c[0]), "+f"(c[1]), "+f"(c[2]), "+f"(c[3])
        : "r"(a[0]), "r"(a[1]), "r"(a[2]), "r"(a[3]), "r"(b[0]), "r"(b[1]));
}
__device__ __forceinline__ void cpa16(uint32_t dst, const void* src, int sz) {
    asm volatile("cp.async.cg.shared.global [%0], [%1], 16, %2;"
                 :: "r"(dst), "l"(src), "r"(sz) : "memory");
}
#define CP_COMMIT() asm volatile("cp.async.commit_group;" ::: "memory")
#define CP_WAIT(n)  asm volatile("cp.async.wait_group %0;" :: "n"(n) : "memory")

// ---------------------------------------------------------------------------
// Conversion kernels
// ---------------------------------------------------------------------------
__global__ void convQf16(const float* __restrict__ q, fp16* __restrict__ o) {
    int i = blockIdx.x * 256 + threadIdx.x;
    if (i >= NTOK * QDIM / 4) return;
    float4 v = ((const float4*)q)[i];
    ((uint2*)o)[i] = make_uint2(
        hpk(__float2half_rn(v.x), __float2half_rn(v.y)),
        hpk(__float2half_rn(v.z), __float2half_rn(v.w)));
}

// transpose + convert to single fp16: in [R][C] f32 -> out [C][R]
__global__ void transConvF16(const float* __restrict__ in, fp16* __restrict__ o,
                             int R, int C) {
    __shared__ float tile[32][33];
    int c0 = blockIdx.x * 32, r0 = blockIdx.y * 32;
    int tx = threadIdx.x, ty = threadIdx.y;    // 32 x 8
    #pragma unroll
    for (int i = 0; i < 4; i++)
        tile[ty + 8 * i][tx] = in[(size_t)(r0 + ty + 8 * i) * C + c0 + tx];
    __syncthreads();
    #pragma unroll
    for (int i = 0; i < 4; i++) {
        float v = tile[tx][ty + 8 * i];
        o[(size_t)(c0 + ty + 8 * i) * R + r0 + tx] = __float2half_rn(v);
    }
}

// ---------------------------------------------------------------------------
// fp16 single-pass GEMM via mma.sync.   HOUT: fp16 vs fp32 output.
// (unchanged from R14 — proven)
// ---------------------------------------------------------------------------
#define TILE_B   10240                   // 128 rows * 40 * 2B
#define STAGE_B  (2 * TILE_B)
#define GSMEM1   (2 * STAGE_B)           // 40960

template<bool HOUT>
__global__ __launch_bounds__(256, 2)
void gemm_f16(const fp16* __restrict__ A, const fp16* __restrict__ B,
              void* __restrict__ C, const float* __restrict__ bias,
              int M, int lda, int ldb, int ldc, int nChunks, int partStride)
{
    extern __shared__ char smem[];
    const uint32_t sm0 = smem_u32(smem);
    const int t = threadIdx.x, lane = t & 31, w = t >> 5;
    const int wr = w & 3, wc = w >> 2;
    const int mrow0 = blockIdx.y * 128;
    const int n0 = blockIdx.x * 128;
    const int k0 = blockIdx.z * nChunks * 32;

    const int row0_ = t >> 2, seg0 = t & 3;
    const int row1_ = (t + 256) >> 2, seg1 = (t + 256) & 3;
    const uint32_t so0 = (uint32_t)(row0_ * 40 + seg0 * 8) * 2;
    const uint32_t so1 = (uint32_t)(row1_ * 40 + seg1 * 8) * 2;
    const int okA0 = ((mrow0 + row0_) < M) ? 16 : 0;
    const int okA1 = ((mrow0 + row1_) < M) ? 16 : 0;
    const size_t gaBase0 = (size_t)(mrow0 + row0_) * lda + seg0 * 8 + k0;
    const size_t gaBase1 = (size_t)(mrow0 + row1_) * lda + seg1 * 8 + k0;
    const size_t gbBase0 = (size_t)(n0 + row0_) * ldb + seg0 * 8 + k0;
    const size_t gbBase1 = (size_t)(n0 + row1_) * ldb + seg1 * 8 + k0;

    const int q = lane >> 3, r8 = lane & 7;
    const uint32_t aoff = (uint32_t)((wr * 32 + r8 + ((q & 1) << 3)) * 40 + ((q >> 1) << 3)) * 2;
    const uint32_t boff = (uint32_t)((wc * 64 + r8 + ((q >> 1) << 3)) * 40 + ((q & 1) << 3)) * 2;

    float c[2][8][4];
    #pragma unroll
    for (int mt = 0; mt < 2; mt++)
        #pragma unroll
        for (int nt = 0; nt < 8; nt++)
            #pragma unroll
            for (int j = 0; j < 4; j++) c[mt][nt][j] = 0.f;

    auto stageLoad = [&](int stage, int kk) {
        uint32_t sb = sm0 + stage * STAGE_B;
        cpa16(sb + 0 * TILE_B + so0, A + gaBase0 + kk, okA0);
        cpa16(sb + 1 * TILE_B + so0, B + gbBase0 + kk, 16);
        cpa16(sb + 0 * TILE_B + so1, A + gaBase1 + kk, okA1);
        cpa16(sb + 1 * TILE_B + so1, B + gbBase1 + kk, 16);
        CP_COMMIT();
    };

    stageLoad(0, 0);

    for (int ch = 0; ch < nChunks; ch++) {
        const int st = ch & 1;
        const bool more = (ch + 1) < nChunks;
        if (more) stageLoad(st ^ 1, (ch + 1) * 32);
        if (more) { CP_WAIT(1); } else { CP_WAIT(0); }
        __syncthreads();

        const uint32_t base = sm0 + st * STAGE_B;
        #pragma unroll
        for (int ks = 0; ks < 2; ks++) {
            uint32_t ah[2][4];
            #pragma unroll
            for (int mt = 0; mt < 2; mt++) {
                uint32_t aA = base + aoff + mt * (16 * 80) + ks * 32;
                ldsm4(ah[mt][0], ah[mt][1], ah[mt][2], ah[mt][3], aA);
            }
            #pragma unroll
            for (int g = 0; g < 4; g++) {
                uint32_t bh[4];
                uint32_t aB = base + TILE_B + boff + g * (16 * 80) + ks * 32;
                ldsm4(bh[0], bh[1], bh[2], bh[3], aB);
                #pragma unroll
                for (int mt = 0; mt < 2; mt++) {
                    mma_f16(c[mt][2*g],   ah[mt], &bh[0]);
                    mma_f16(c[mt][2*g+1], ah[mt], &bh[2]);
                }
            }
        }
        __syncthreads();
    }

    const int crow = mrow0 + wr * 32 + (lane >> 2);
    const int ccol = n0 + wc * 64 + (lane & 3) * 2;
    #pragma unroll
    for (int mt = 0; mt < 2; mt++) {
        #pragma unroll
        for (int nt = 0; nt < 8; nt++) {
            int col = ccol + nt * 8;
            float b0 = 0.f, b1 = 0.f;
            if (bias) { b0 = bias[col]; b1 = bias[col + 1]; }
            int r0 = crow + mt * 16;
            int r1 = r0 + 8;
            if (HOUT) {
                fp16* Cp = (fp16*)C + (size_t)blockIdx.z * partStride;
                if (r0 < M)
                    *(__half2*)(Cp + (size_t)r0 * ldc + col) =
                        __floats2half2_rn(c[mt][nt][0] + b0, c[mt][nt][1] + b1);
                if (r1 < M)
                    *(__half2*)(Cp + (size_t)r1 * ldc + col) =
                        __floats2half2_rn(c[mt][nt][2] + b0, c[mt][nt][3] + b1);
            } else {
                float* Cp = (float*)C + (size_t)blockIdx.z * partStride;
                if (r0 < M)
                    *(float2*)(Cp + (size_t)r0 * ldc + col) =
                        make_float2(c[mt][nt][0] + b0, c[mt][nt][1] + b1);
                if (r1 < M)
                    *(float2*)(Cp + (size_t)r1 * ldc + col) =
                        make_float2(c[mt][nt][2] + b0, c[mt][nt][3] + b1);
            }
        }
    }
}

// ---------------------------------------------------------------------------
// Block reduction of (sum, sumsq) over 128 threads / 4 warps.
// ---------------------------------------------------------------------------
__device__ __forceinline__ void blockReduce2_128(float& s, float& q, float* red) {
    #pragma unroll
    for (int o = 16; o > 0; o >>= 1) {
        s += __shfl_xor_sync(0xffffffffu, s, o);
        q += __shfl_xor_sync(0xffffffffu, q, o);
    }
    const int t = threadIdx.x;
    if ((t & 31) == 0) { red[t >> 5] = s; red[4 + (t >> 5)] = q; }
    __syncthreads();
    s = red[0] + red[1] + red[2] + red[3];
    q = red[4] + red[5] + red[6] + red[7];
    __syncthreads();
}

// ---------------------------------------------------------------------------
// Fused middle v4: 128 threads/CTA.
//   stage1 (scalar f32x2): out1 = relu(LN(x[32,64] @ M[64,64])) -> fp16 smem,
//          stored transposed as B-operand layout [64 o][32 p], pitch 40.
//   stage2 (mma.sync):  out2[128,64] = S[128,32] @ out1;  S staged fp16
//          pitch-40 as A operand. LN on fp32 accumulators; Z from fragments.
// ---------------------------------------------------------------------------
__global__ __launch_bounds__(128)
void midkernel(const float* __restrict__ x, const fp16* __restrict__ params,
               fp16* __restrict__ Z)
{
    __shared__ float sX[2048];             // x [32][64]
    __shared__ float sM[4096];             // M [64][64]
    __shared__ fp16  sS[128 * 40];         // S [128 q][32 p], pitch 40 (A op)
    __shared__ fp16  sO1T[64 * 40];        // out1^T [64 o][32 p], pitch 40 (B op)
    __shared__ float red[8];

    const int ng = blockIdx.x;
    const int t  = threadIdx.x;            // 0..127
    const int lane = t & 31, wr = t >> 5;
    const float* xb = x + (size_t)ng * (INP * EIN);
    const fp16* pb = params + (size_t)(ng >> 2) * PCOLS + (size_t)(ng & 3) * TOTALP;

    {   // ---- cooperative loads ----
        const float4* x4 = (const float4*)xb;
        const uint4* m4 = (const uint4*)pb;            // M: 4096 halves
        const uint4* s4 = (const uint4*)(pb + 4096);   // S: 8192 B = 512 uint4
        ((float4*)sX)[t]       = x4[t];
        ((float4*)sX)[t + 128] = x4[t + 128];
        ((float4*)sX)[t + 256] = x4[t + 256];
        ((float4*)sX)[t + 384] = x4[t + 384];
        #pragma unroll
        for (int i = 0; i < 4; i++) {
            int idx = t + 128 * i;
            uint4 v = m4[idx];
            float2 f0 = __half22float2(*(__half2*)&v.x);
            float2 f1 = __half22float2(*(__half2*)&v.y);
            float2 f2 = __half22float2(*(__half2*)&v.z);
            float2 f3 = __half22float2(*(__half2*)&v.w);
            float4* d = (float4*)(sM + idx * 8);
            d[0] = make_float4(f0.x, f0.y, f1.x, f1.y);
            d[1] = make_float4(f2.x, f2.y, f3.x, f3.y);
        }
        // S raw copy into pitch-40 rows: row r (32 halves = 4 segs of 8)
        #pragma unroll
        for (int i = 0; i < 4; i++) {
            int idx = t + 128 * i;          // 0..511
            int r = idx >> 2, s = idx & 3;
            *(uint4*)(sS + r * 40 + s * 8) = s4[idx];
        }
    }
    __syncthreads();

    // ---- stage 1 (scalar): out1[p][o] = sum_c x[p][c]*M[c][o] ----
    const int p0 = (t >> 3) << 1;          // 2 rows per thread
    const int og = (t & 7) << 3;           // 8 cols per thread
    ull acc1[2][4];
    #pragma unroll
    for (int i = 0; i < 2; i++)
        #pragma unroll
        for (int j = 0; j < 4; j++) acc1[i][j] = 0ull;

    #pragma unroll 4
    for (int cix = 0; cix < 64; cix++) {
        float xv0 = sX[p0 * 64 + cix];
        float xv1 = sX[(p0 + 1) * 64 + cix];
        ull x0 = pack2(xv0, xv0);
        ull x1 = pack2(xv1, xv1);
        const ulonglong2* mp = (const ulonglong2*)(sM + cix * 64 + og);
        ulonglong2 m0 = mp[0], m1 = mp[1];
        fma2(acc1[0][0], x0, m0.x); fma2(acc1[0][1], x0, m0.y);
        fma2(acc1[0][2], x0, m1.x); fma2(acc1[0][3], x0, m1.y);
        fma2(acc1[1][0], x1, m0.x); fma2(acc1[1][1], x1, m0.y);
        fma2(acc1[1][2], x1, m1.x); fma2(acc1[1][3], x1, m1.y);
    }
    float v1[2][8];
    float s1 = 0.f, q1 = 0.f;
    #pragma unroll
    for (int i = 0; i < 2; i++) {
        unpack2(acc1[i][0], v1[i][0], v1[i][1]); unpack2(acc1[i][1], v1[i][2], v1[i][3]);
        unpack2(acc1[i][2], v1[i][4], v1[i][5]); unpack2(acc1[i][3], v1[i][6], v1[i][7]);
        #pragma unroll
        for (int j = 0; j < 8; j++) { s1 += v1[i][j]; q1 += v1[i][j] * v1[i][j]; }
    }
    __syncthreads();
    blockReduce2_128(s1, q1, red);
    {
        float mean = s1 * (1.f / 2048.f);
        float var  = q1 * (1.f / 2048.f) - mean * mean;
        float rs   = rsqrtf(var + 1e-5f);
        // store relu(LN(out1)) transposed -> sO1T[o][p] fp16 (B-operand layout)
        #pragma unroll
        for (int i = 0; i < 2; i++)
            #pragma unroll
            for (int j = 0; j < 8; j++)
                sO1T[(og + j) * 40 + p0 + i] =
                    __float2half_rn(fmaxf((v1[i][j] - mean) * rs, 0.f));
    }
    __syncthreads();

    // ---- stage 2 (mma): out2[128,64] = S @ out1 ----
    const uint32_t sSb  = smem_u32(sS);
    const uint32_t sOb  = smem_u32(sO1T);
    const int q = lane >> 3, r8 = lane & 7;
    const uint32_t aoff = (uint32_t)((wr * 32 + r8 + ((q & 1) << 3)) * 40 + ((q >> 1) << 3)) * 2;
    const uint32_t boff = (uint32_t)((r8 + ((q >> 1) << 3)) * 40 + ((q & 1) << 3)) * 2;

    float c[2][8][4];
    #pragma unroll
    for (int mt = 0; mt < 2; mt++)
        #pragma unroll
        for (int nt = 0; nt < 8; nt++)
            #pragma unroll
            for (int j = 0; j < 4; j++) c[mt][nt][j] = 0.f;

    #pragma unroll
    for (int ks = 0; ks < 2; ks++) {
        uint32_t ah[2][4];
        #pragma unroll
        for (int mt = 0; mt < 2; mt++)
            ldsm4(ah[mt][0], ah[mt][1], ah[mt][2], ah[mt][3],
                  sSb + aoff + mt * (16 * 80) + ks * 32);
        #pragma unroll
        for (int g = 0; g < 4; g++) {
            uint32_t bh[4];
            ldsm4(bh[0], bh[1], bh[2], bh[3],
                  sOb + boff + g * (16 * 80) + ks * 32);
            #pragma unroll
            for (int mt = 0; mt < 2; mt++) {
                mma_f16(c[mt][2*g],   ah[mt], &bh[0]);
                mma_f16(c[mt][2*g+1], ah[mt], &bh[2]);
            }
        }
    }

    // ---- LN over out2 (8192 elements) on fp32 accumulators ----
    float s2 = 0.f, q2 = 0.f;
    #pragma unroll
    for (int mt = 0; mt < 2; mt++)
        #pragma unroll
        for (int nt = 0; nt < 8; nt++)
            #pragma unroll
            for (int j = 0; j < 4; j++) {
                float v = c[mt][nt][j];
                s2 += v; q2 += v * v;
            }
    blockReduce2_128(s2, q2, red);
    float mean2 = s2 * (1.f / 8192.f);
    float var2  = q2 * (1.f / 8192.f) - mean2 * mean2;
    float rs2   = rsqrtf(var2 + 1e-5f);

    // ---- store Z from fragments ----
    fp16* zb = Z + (size_t)(ng >> 2) * PCOLS + (size_t)(ng & 3) * TOTALP;
    const int crow = wr * 32 + (lane >> 2);
    const int ccol = (lane & 3) * 2;
    #pragma unroll
    for (int mt = 0; mt < 2; mt++) {
        #pragma unroll
        for (int nt = 0; nt < 8; nt++) {
            int col = ccol + nt * 8;
            int r0 = crow + mt * 16;
            float a0 = fmaxf((c[mt][nt][0] - mean2) * rs2, 0.f);
            float a1 = fmaxf((c[mt][nt][1] - mean2) * rs2, 0.f);
            float a2 = fmaxf((c[mt][nt][2] - mean2) * rs2, 0.f);
            float a3 = fmaxf((c[mt][nt][3] - mean2) * rs2, 0.f);
            *(__half2*)(zb + (size_t)r0 * 64 + col)       = __floats2half2_rn(a0, a1);
            *(__half2*)(zb + (size_t)(r0 + 8) * 64 + col) = __floats2half2_rn(a2, a3);
        }
    }
}

// ---------------------------------------------------------------------------
__global__ void finalReduce(const float* __restrict__ part,
                            const float* __restrict__ query,
                            const float* __restrict__ bo,
                            float* __restrict__ out)
{
    int i = blockIdx.x * 256 + threadIdx.x;
    if (i >= NTOK * QDIM) return;
    float s = query[i] + bo[i & (QDIM - 1)];
    #pragma unroll
    for (int z = 0; z < SPLITK; z++)
        s += part[(size_t)z * NTOK * QDIM + i];
    out[i] = s;
}

// ---------------------------------------------------------------------------
extern "C" void kernel_launch(void* const* d_in, const int* in_sizes, int n_in,
                              void* d_out, int out_size)
{
    const float* x     = (const float*)d_in[0];
    const float* query = (const float*)d_in[1];
    const float* Wp    = (const float*)d_in[2];
    const float* bp    = (const float*)d_in[3];
    const float* Wo    = (const float*)d_in[4];
    const float* bo    = (const float*)d_in[5];
    float* out = (float*)d_out;

    float* pPart;
    fp16 *pParams, *pQ, *pWpT, *pWoT, *pZ;
    cudaGetSymbolAddress((void**)&pParams, g_params);
    cudaGetSymbolAddress((void**)&pPart, g_part);
    cudaGetSymbolAddress((void**)&pQ, g_q16);
    cudaGetSymbolAddress((void**)&pWpT, g_wpT);
    cudaGetSymbolAddress((void**)&pWoT, g_woT);
    cudaGetSymbolAddress((void**)&pZ, g_z);

    static cudaStream_t s1 = nullptr, s2 = nullptr;
    static cudaEvent_t evRoot = nullptr, evWp = nullptr, evWo = nullptr;
    if (!s1) {
        cudaStreamCreateWithFlags(&s1, cudaStreamNonBlocking);
        cudaStreamCreateWithFlags(&s2, cudaStreamNonBlocking);
        cudaEventCreateWithFlags(&evRoot, cudaEventDisableTiming);
        cudaEventCreateWithFlags(&evWp, cudaEventDisableTiming);
        cudaEventCreateWithFlags(&evWo, cudaEventDisableTiming);
        cudaFuncSetAttribute((const void*)gemm_f16<true>,
                             cudaFuncAttributeMaxDynamicSharedMemorySize, GSMEM1);
        cudaFuncSetAttribute((const void*)gemm_f16<false>,
                             cudaFuncAttributeMaxDynamicSharedMemorySize, GSMEM1);
    }

    cudaEventRecord(evRoot, 0);
    cudaStreamWaitEvent(s1, evRoot, 0);
    cudaStreamWaitEvent(s2, evRoot, 0);

    convQf16<<<(NTOK * QDIM / 4 + 255) / 256, 256>>>(query, pQ);
    transConvF16<<<dim3(PCOLS / 32, QDIM / 32), dim3(32, 8), 0, s1>>>(Wp, pWpT, QDIM, PCOLS);
    transConvF16<<<dim3(QDIM / 32, PCOLS / 32), dim3(32, 8), 0, s2>>>(Wo, pWoT, PCOLS, QDIM);

    cudaEventRecord(evWp, s1);
    cudaStreamWaitEvent(0, evWp, 0);

    // GEMM1: params(fp16) = q @ Wp + bp  (fp16 1-pass, K=256 -> 8 chunks)
    gemm_f16<true><<<dim3(PCOLS / 128, 29, 1), 256, GSMEM1>>>(
        pQ, pWpT, pParams, bp, NTOK, QDIM, QDIM, PCOLS, 8, 0);

    midkernel<<<NTOK * 4, 128>>>(x, pParams, pZ);

    cudaEventRecord(evWo, s2);
    cudaStreamWaitEvent(0, evWo, 0);

    // GEMM3: part[z] = Z[:, z*1024:(z+1)*1024] @ Wo-chunk  (fp16 1-pass)
    gemm_f16<false><<<dim3(QDIM / 128, 29, SPLITK), 256, GSMEM1>>>(
        pZ, pWoT, pPart, nullptr,
        NTOK, PCOLS, PCOLS, QDIM, (PCOLS / SPLITK) / 32, (int)((size_t)NTOK * QDIM));

    finalReduce<<<(NTOK * QDIM + 255) / 256, 256>>>(pPart, query, bo, out);
}

// round 16
// speedup vs baseline: 2.8916x; 1.3535x over previous
#include <cuda_runtime.h>
#include <cuda_bf16.h>
#include <cuda_fp16.h>
#include <cstdint>

// ---------------------------------------------------------------------------
// AdaptiveMixing on GB300 (compute_103 portable path):
//   params = query @ Wp + bp   [3600 x 32768] fp16  (fp16 1-pass mma.sync)
//   per (tok,grp): both mixes on tensor cores (x truncated fp16),
//                  LN on fp32 accumulators
//   out = Z @ Wo + bo + query  [3600 x 256]         (fp16 1-pass mma.sync)
// R16: mid stage-1 on mma.sync as well (M already fp16 [k][n] -> ldmatrix.trans).
// Quadrature error model: ~2.4-2.8e-4 per fp16 truncation; predicted ~6.5e-4.
// ---------------------------------------------------------------------------
#define NTOK   3600
#define QDIM   256
#define PCOLS  32768
#define TOTALP 8192
#define INP    32
#define EIN    64
#define SPLITK 32

typedef unsigned long long ull;
typedef __half fp16;

// ------------------------- device scratch (no allocs) ----------------------
__device__ fp16  g_params[(size_t)NTOK * PCOLS];
__device__ fp16  g_q16[(size_t)NTOK * QDIM];
__device__ fp16  g_wpT[(size_t)PCOLS * QDIM];
__device__ fp16  g_woT[(size_t)QDIM * PCOLS];
__device__ fp16  g_z[(size_t)NTOK * PCOLS];
__device__ float g_part[(size_t)SPLITK * NTOK * QDIM];

// ----------------------------- helpers -------------------------------------
__device__ __forceinline__ unsigned hpk(fp16 a, fp16 b) {
    return (unsigned)__half_as_ushort(a) | ((unsigned)__half_as_ushort(b) << 16);
}
__device__ __forceinline__ uint32_t smem_u32(const void* p) {
    uint32_t a;
    asm("{ .reg .u64 t; cvta.to.shared.u64 t, %1; cvt.u32.u64 %0, t; }" : "=r"(a) : "l"(p));
    return a;
}
__device__ __forceinline__ void ldsm4(uint32_t& r0, uint32_t& r1, uint32_t& r2, uint32_t& r3,
                                      uint32_t addr) {
    asm volatile("ldmatrix.sync.aligned.m8n8.x4.shared.b16 {%0,%1,%2,%3}, [%4];"
                 : "=r"(r0), "=r"(r1), "=r"(r2), "=r"(r3) : "r"(addr));
}
__device__ __forceinline__ void ldsm4t(uint32_t& r0, uint32_t& r1, uint32_t& r2, uint32_t& r3,
                                       uint32_t addr) {
    asm volatile("ldmatrix.sync.aligned.m8n8.x4.trans.shared.b16 {%0,%1,%2,%3}, [%4];"
                 : "=r"(r0), "=r"(r1), "=r"(r2), "=r"(r3) : "r"(addr));
}
__device__ __forceinline__ void mma_f16(float* c, const uint32_t* a, const uint32_t* b) {
    asm volatile(
        "mma.sync.aligned.m16n8k16.row.col.f32.f16.f16.f32 "
        "{%0,%1,%2,%3}, {%4,%5,%6,%7}, {%8,%9}, {%0,%1,%2,%3};"
        : "+f"(c[0]), "+f"(c[1]), "+f"(c[2]), "+f"(c[3])
        : "r"(a[0]), "r"(a[1]), "r"(a[2]), "r"(a[3]), "r"(b[0]), "r"(b[1]));
}
__device__ __forceinline__ void cpa16(uint32_t dst, const void* src, int sz) {
    asm volatile("cp.async.cg.shared.global [%0], [%1], 16, %2;"
                 :: "r"(dst), "l"(src), "r"(sz) : "memory");
}
#define CP_COMMIT() asm volatile("cp.async.commit_group;" ::: "memory")
#define CP_WAIT(n)  asm volatile("cp.async.wait_group %0;" :: "n"(n) : "memory")

// ---------------------------------------------------------------------------
// Conversion kernels
// ---------------------------------------------------------------------------
__global__ void convQf16(const float* __restrict__ q, fp16* __restrict__ o) {
    int i = blockIdx.x * 256 + threadIdx.x;
    if (i >= NTOK * QDIM / 4) return;
    float4 v = ((const float4*)q)[i];
    ((uint2*)o)[i] = make_uint2(
        hpk(__float2half_rn(v.x), __float2half_rn(v.y)),
        hpk(__float2half_rn(v.z), __float2half_rn(v.w)));
}

// transpose + convert to single fp16: in [R][C] f32 -> out [C][R]
__global__ void transConvF16(const float* __restrict__ in, fp16* __restrict__ o,
                             int R, int C) {
    __shared__ float tile[32][33];
    int c0 = blockIdx.x * 32, r0 = blockIdx.y * 32;
    int tx = threadIdx.x, ty = threadIdx.y;    // 32 x 8
    #pragma unroll
    for (int i = 0; i < 4; i++)
        tile[ty + 8 * i][tx] = in[(size_t)(r0 + ty + 8 * i) * C + c0 + tx];
    __syncthreads();
    #pragma unroll
    for (int i = 0; i < 4; i++) {
        float v = tile[tx][ty + 8 * i];
        o[(size_t)(c0 + ty + 8 * i) * R + r0 + tx] = __float2half_rn(v);
    }
}

// ---------------------------------------------------------------------------
// fp16 single-pass GEMM via mma.sync.   HOUT: fp16 vs fp32 output.
// (unchanged from R14 — proven)
// ---------------------------------------------------------------------------
#define TILE_B   10240                   // 128 rows * 40 * 2B
#define STAGE_B  (2 * TILE_B)
#define GSMEM1   (2 * STAGE_B)           // 40960

template<bool HOUT>
__global__ __launch_bounds__(256, 2)
void gemm_f16(const fp16* __restrict__ A, const fp16* __restrict__ B,
              void* __restrict__ C, const float* __restrict__ bias,
              int M, int lda, int ldb, int ldc, int nChunks, int partStride)
{
    extern __shared__ char smem[];
    const uint32_t sm0 = smem_u32(smem);
    const int t = threadIdx.x, lane = t & 31, w = t >> 5;
    const int wr = w & 3, wc = w >> 2;
    const int mrow0 = blockIdx.y * 128;
    const int n0 = blockIdx.x * 128;
    const int k0 = blockIdx.z * nChunks * 32;

    const int row0_ = t >> 2, seg0 = t & 3;
    const int row1_ = (t + 256) >> 2, seg1 = (t + 256) & 3;
    const uint32_t so0 = (uint32_t)(row0_ * 40 + seg0 * 8) * 2;
    const uint32_t so1 = (uint32_t)(row1_ * 40 + seg1 * 8) * 2;
    const int okA0 = ((mrow0 + row0_) < M) ? 16 : 0;
    const int okA1 = ((mrow0 + row1_) < M) ? 16 : 0;
    const size_t gaBase0 = (size_t)(mrow0 + row0_) * lda + seg0 * 8 + k0;
    const size_t gaBase1 = (size_t)(mrow0 + row1_) * lda + seg1 * 8 + k0;
    const size_t gbBase0 = (size_t)(n0 + row0_) * ldb + seg0 * 8 + k0;
    const size_t gbBase1 = (size_t)(n0 + row1_) * ldb + seg1 * 8 + k0;

    const int q = lane >> 3, r8 = lane & 7;
    const uint32_t aoff = (uint32_t)((wr * 32 + r8 + ((q & 1) << 3)) * 40 + ((q >> 1) << 3)) * 2;
    const uint32_t boff = (uint32_t)((wc * 64 + r8 + ((q >> 1) << 3)) * 40 + ((q & 1) << 3)) * 2;

    float c[2][8][4];
    #pragma unroll
    for (int mt = 0; mt < 2; mt++)
        #pragma unroll
        for (int nt = 0; nt < 8; nt++)
            #pragma unroll
            for (int j = 0; j < 4; j++) c[mt][nt][j] = 0.f;

    auto stageLoad = [&](int stage, int kk) {
        uint32_t sb = sm0 + stage * STAGE_B;
        cpa16(sb + 0 * TILE_B + so0, A + gaBase0 + kk, okA0);
        cpa16(sb + 1 * TILE_B + so0, B + gbBase0 + kk, 16);
        cpa16(sb + 0 * TILE_B + so1, A + gaBase1 + kk, okA1);
        cpa16(sb + 1 * TILE_B + so1, B + gbBase1 + kk, 16);
        CP_COMMIT();
    };

    stageLoad(0, 0);

    for (int ch = 0; ch < nChunks; ch++) {
        const int st = ch & 1;
        const bool more = (ch + 1) < nChunks;
        if (more) stageLoad(st ^ 1, (ch + 1) * 32);
        if (more) { CP_WAIT(1); } else { CP_WAIT(0); }
        __syncthreads();

        const uint32_t base = sm0 + st * STAGE_B;
        #pragma unroll
        for (int ks = 0; ks < 2; ks++) {
            uint32_t ah[2][4];
            #pragma unroll
            for (int mt = 0; mt < 2; mt++) {
                uint32_t aA = base + aoff + mt * (16 * 80) + ks * 32;
                ldsm4(ah[mt][0], ah[mt][1], ah[mt][2], ah[mt][3], aA);
            }
            #pragma unroll
            for (int g = 0; g < 4; g++) {
                uint32_t bh[4];
                uint32_t aB = base + TILE_B + boff + g * (16 * 80) + ks * 32;
                ldsm4(bh[0], bh[1], bh[2], bh[3], aB);
                #pragma unroll
                for (int mt = 0; mt < 2; mt++) {
                    mma_f16(c[mt][2*g],   ah[mt], &bh[0]);
                    mma_f16(c[mt][2*g+1], ah[mt], &bh[2]);
                }
            }
        }
        __syncthreads();
    }

    const int crow = mrow0 + wr * 32 + (lane >> 2);
    const int ccol = n0 + wc * 64 + (lane & 3) * 2;
    #pragma unroll
    for (int mt = 0; mt < 2; mt++) {
        #pragma unroll
        for (int nt = 0; nt < 8; nt++) {
            int col = ccol + nt * 8;
            float b0 = 0.f, b1 = 0.f;
            if (bias) { b0 = bias[col]; b1 = bias[col + 1]; }
            int r0 = crow + mt * 16;
            int r1 = r0 + 8;
            if (HOUT) {
                fp16* Cp = (fp16*)C + (size_t)blockIdx.z * partStride;
                if (r0 < M)
                    *(__half2*)(Cp + (size_t)r0 * ldc + col) =
                        __floats2half2_rn(c[mt][nt][0] + b0, c[mt][nt][1] + b1);
                if (r1 < M)
                    *(__half2*)(Cp + (size_t)r1 * ldc + col) =
                        __floats2half2_rn(c[mt][nt][2] + b0, c[mt][nt][3] + b1);
            } else {
                float* Cp = (float*)C + (size_t)blockIdx.z * partStride;
                if (r0 < M)
                    *(float2*)(Cp + (size_t)r0 * ldc + col) =
                        make_float2(c[mt][nt][0] + b0, c[mt][nt][1] + b1);
                if (r1 < M)
                    *(float2*)(Cp + (size_t)r1 * ldc + col) =
                        make_float2(c[mt][nt][2] + b0, c[mt][nt][3] + b1);
            }
        }
    }
}

// ---------------------------------------------------------------------------
// Block reduction of (sum, sumsq) over 128 threads / 4 warps.
// ---------------------------------------------------------------------------
__device__ __forceinline__ void blockReduce2_128(float& s, float& q, float* red) {
    #pragma unroll
    for (int o = 16; o > 0; o >>= 1) {
        s += __shfl_xor_sync(0xffffffffu, s, o);
        q += __shfl_xor_sync(0xffffffffu, q, o);
    }
    const int t = threadIdx.x;
    if ((t & 31) == 0) { red[t >> 5] = s; red[4 + (t >> 5)] = q; }
    __syncthreads();
    s = red[0] + red[1] + red[2] + red[3];
    q = red[4] + red[5] + red[6] + red[7];
    __syncthreads();
}

// ---------------------------------------------------------------------------
// Fused middle v5: both stages on mma.sync. 128 threads / 4 warps per CTA.
//   stage1: out1[32,64] = x[32,64]@M[64,64]; x fp16 pitch-72 (A),
//           M fp16 [k][n] pitch-72 via ldmatrix.trans (B). Warp w owns n-block
//           w*16 (2 n8-tiles); LN on fragments -> relu -> fp16 sO1T[o][p].
//   stage2: out2[128,64] = S[128,32]@out1; S pitch-40 (A), sO1T pitch-40 (B).
// ---------------------------------------------------------------------------
__global__ __launch_bounds__(128)
void midkernel(const float* __restrict__ x, const fp16* __restrict__ params,
               fp16* __restrict__ Z)
{
    __shared__ fp16  sXh[32 * 72];         // x fp16, pitch 72  (4608 B)
    __shared__ fp16  sMh[64 * 72];         // M fp16 [c][o], pitch 72 (9216 B)
    __shared__ fp16  sS[128 * 40];         // S [q][p], pitch 40 (A op stage2)
    __shared__ fp16  sO1T[64 * 40];        // out1^T [o][p], pitch 40 (B op stage2)
    __shared__ float red[8];

    const int ng = blockIdx.x;
    const int t  = threadIdx.x;            // 0..127
    const int lane = t & 31, w = t >> 5;
    const float* xb = x + (size_t)ng * (INP * EIN);
    const fp16* pb = params + (size_t)(ng >> 2) * PCOLS + (size_t)(ng & 3) * TOTALP;

    {   // ---- cooperative loads ----
        const float4* x4 = (const float4*)xb;
        const uint4* m4 = (const uint4*)pb;            // M: 4096 halves = 512 uint4
        const uint4* s4 = (const uint4*)(pb + 4096);   // S: 512 uint4
        // x: fp32 -> fp16, [32][64] -> pitch 72
        #pragma unroll
        for (int i = 0; i < 4; i++) {
            int idx = t + 128 * i;          // 0..511 float4s
            float4 v = x4[idx];
            int g = idx << 2;               // linear elem
            int row = g >> 6, col = g & 63;
            fp16* d = sXh + row * 72 + col;
            *(uint2*)d = make_uint2(
                hpk(__float2half_rn(v.x), __float2half_rn(v.y)),
                hpk(__float2half_rn(v.z), __float2half_rn(v.w)));
        }
        // M: raw copy [64 rows][64 cols] -> pitch 72 (8 uint4 per row)
        #pragma unroll
        for (int i = 0; i < 4; i++) {
            int idx = t + 128 * i;          // 0..511
            int row = idx >> 3, seg = idx & 7;
            *(uint4*)(sMh + row * 72 + seg * 8) = m4[idx];
        }
        // S: raw copy [128 rows][32 cols] -> pitch 40 (4 uint4 per row)
        #pragma unroll
        for (int i = 0; i < 4; i++) {
            int idx = t + 128 * i;
            int r = idx >> 2, s = idx & 3;
            *(uint4*)(sS + r * 40 + s * 8) = s4[idx];
        }
    }
    __syncthreads();

    const int q = lane >> 3, r8 = lane & 7;
    const uint32_t sXb = smem_u32(sXh);
    const uint32_t sMb = smem_u32(sMh);

    // ---- stage 1 (mma): out1 = x @ M ----
    // A frag addr (pitch 72): row = mt*16 + (q&1)*8 + r8, col = ks*16 + (q>>1)*8
    // B frag addr (trans, pitch 72): krow = ks*16 + (q&1)*8 + r8, ncol = w*16 + (q>>1)*8
    float c1[2][2][4];
    #pragma unroll
    for (int mt = 0; mt < 2; mt++)
        #pragma unroll
        for (int nt = 0; nt < 2; nt++)
            #pragma unroll
            for (int j = 0; j < 4; j++) c1[mt][nt][j] = 0.f;

    #pragma unroll
    for (int ks = 0; ks < 4; ks++) {
        uint32_t ah[2][4];
        #pragma unroll
        for (int mt = 0; mt < 2; mt++)
            ldsm4(ah[mt][0], ah[mt][1], ah[mt][2], ah[mt][3],
                  sXb + (uint32_t)((mt * 16 + ((q & 1) << 3) + r8) * 72
                                   + ks * 16 + ((q >> 1) << 3)) * 2);
        uint32_t bh[4];
        ldsm4t(bh[0], bh[1], bh[2], bh[3],
               sMb + (uint32_t)((ks * 16 + ((q & 1) << 3) + r8) * 72
                                + w * 16 + ((q >> 1) << 3)) * 2);
        #pragma unroll
        for (int mt = 0; mt < 2; mt++) {
            mma_f16(c1[mt][0], ah[mt], &bh[0]);
            mma_f16(c1[mt][1], ah[mt], &bh[2]);
        }
    }

    // LN over out1 (2048 elems; 16 per thread)
    float s1 = 0.f, q1 = 0.f;
    #pragma unroll
    for (int mt = 0; mt < 2; mt++)
        #pragma unroll
        for (int nt = 0; nt < 2; nt++)
            #pragma unroll
            for (int j = 0; j < 4; j++) {
                float v = c1[mt][nt][j];
                s1 += v; q1 += v * v;
            }
    blockReduce2_128(s1, q1, red);
    {
        float mean = s1 * (1.f / 2048.f);
        float var  = q1 * (1.f / 2048.f) - mean * mean;
        float rs   = rsqrtf(var + 1e-5f);
        // scatter relu(LN(out1)) -> sO1T[o][p] fp16, pitch 40
        const int prow = lane >> 2;              // + mt*16 (+8 for c2/c3)
        const int ocol = w * 16 + (lane & 3) * 2; // + nt*8 (+1 for odd)
        #pragma unroll
        for (int mt = 0; mt < 2; mt++)
            #pragma unroll
            for (int nt = 0; nt < 2; nt++) {
                int o0 = ocol + nt * 8;
                int p0 = prow + mt * 16;
                sO1T[(o0)     * 40 + p0]     = __float2half_rn(fmaxf((c1[mt][nt][0] - mean) * rs, 0.f));
                sO1T[(o0 + 1) * 40 + p0]     = __float2half_rn(fmaxf((c1[mt][nt][1] - mean) * rs, 0.f));
                sO1T[(o0)     * 40 + p0 + 8] = __float2half_rn(fmaxf((c1[mt][nt][2] - mean) * rs, 0.f));
                sO1T[(o0 + 1) * 40 + p0 + 8] = __float2half_rn(fmaxf((c1[mt][nt][3] - mean) * rs, 0.f));
            }
    }
    __syncthreads();

    // ---- stage 2 (mma): out2[128,64] = S @ out1 ----
    const uint32_t sSb = smem_u32(sS);
    const uint32_t sOb = smem_u32(sO1T);
    const uint32_t aoff = (uint32_t)((w * 32 + r8 + ((q & 1) << 3)) * 40 + ((q >> 1) << 3)) * 2;
    const uint32_t boff = (uint32_t)((r8 + ((q >> 1) << 3)) * 40 + ((q & 1) << 3)) * 2;

    float c[2][8][4];
    #pragma unroll
    for (int mt = 0; mt < 2; mt++)
        #pragma unroll
        for (int nt = 0; nt < 8; nt++)
            #pragma unroll
            for (int j = 0; j < 4; j++) c[mt][nt][j] = 0.f;

    #pragma unroll
    for (int ks = 0; ks < 2; ks++) {
        uint32_t ah[2][4];
        #pragma unroll
        for (int mt = 0; mt < 2; mt++)
            ldsm4(ah[mt][0], ah[mt][1], ah[mt][2], ah[mt][3],
                  sSb + aoff + mt * (16 * 80) + ks * 32);
        #pragma unroll
        for (int g = 0; g < 4; g++) {
            uint32_t bh[4];
            ldsm4(bh[0], bh[1], bh[2], bh[3],
                  sOb + boff + g * (16 * 80) + ks * 32);
            #pragma unroll
            for (int mt = 0; mt < 2; mt++) {
                mma_f16(c[mt][2*g],   ah[mt], &bh[0]);
                mma_f16(c[mt][2*g+1], ah[mt], &bh[2]);
            }
        }
    }

    // LN over out2 (8192 elems) on fp32 accumulators
    float s2 = 0.f, q2 = 0.f;
    #pragma unroll
    for (int mt = 0; mt < 2; mt++)
        #pragma unroll
        for (int nt = 0; nt < 8; nt++)
            #pragma unroll
            for (int j = 0; j < 4; j++) {
                float v = c[mt][nt][j];
                s2 += v; q2 += v * v;
            }
    blockReduce2_128(s2, q2, red);
    float mean2 = s2 * (1.f / 8192.f);
    float var2  = q2 * (1.f / 8192.f) - mean2 * mean2;
    float rs2   = rsqrtf(var2 + 1e-5f);

    // store Z from fragments
    fp16* zb = Z + (size_t)(ng >> 2) * PCOLS + (size_t)(ng & 3) * TOTALP;
    const int crow = w * 32 + (lane >> 2);
    const int ccol = (lane & 3) * 2;
    #pragma unroll
    for (int mt = 0; mt < 2; mt++) {
        #pragma unroll
        for (int nt = 0; nt < 8; nt++) {
            int col = ccol + nt * 8;
            int r0 = crow + mt * 16;
            float a0 = fmaxf((c[mt][nt][0] - mean2) * rs2, 0.f);
            float a1 = fmaxf((c[mt][nt][1] - mean2) * rs2, 0.f);
            float a2 = fmaxf((c[mt][nt][2] - mean2) * rs2, 0.f);
            float a3 = fmaxf((c[mt][nt][3] - mean2) * rs2, 0.f);
            *(__half2*)(zb + (size_t)r0 * 64 + col)       = __floats2half2_rn(a0, a1);
            *(__half2*)(zb + (size_t)(r0 + 8) * 64 + col) = __floats2half2_rn(a2, a3);
        }
    }
}

// ---------------------------------------------------------------------------
__global__ void finalReduce(const float* __restrict__ part,
                            const float* __restrict__ query,
                            const float* __restrict__ bo,
                            float* __restrict__ out)
{
    int i = blockIdx.x * 256 + threadIdx.x;
    if (i >= NTOK * QDIM) return;
    float s = query[i] + bo[i & (QDIM - 1)];
    #pragma unroll
    for (int z = 0; z < SPLITK; z++)
        s += part[(size_t)z * NTOK * QDIM + i];
    out[i] = s;
}

// ---------------------------------------------------------------------------
extern "C" void kernel_launch(void* const* d_in, const int* in_sizes, int n_in,
                              void* d_out, int out_size)
{
    const float* x     = (const float*)d_in[0];
    const float* query = (const float*)d_in[1];
    const float* Wp    = (const float*)d_in[2];
    const float* bp    = (const float*)d_in[3];
    const float* Wo    = (const float*)d_in[4];
    const float* bo    = (const float*)d_in[5];
    float* out = (float*)d_out;

    float* pPart;
    fp16 *pParams, *pQ, *pWpT, *pWoT, *pZ;
    cudaGetSymbolAddress((void**)&pParams, g_params);
    cudaGetSymbolAddress((void**)&pPart, g_part);
    cudaGetSymbolAddress((void**)&pQ, g_q16);
    cudaGetSymbolAddress((void**)&pWpT, g_wpT);
    cudaGetSymbolAddress((void**)&pWoT, g_woT);
    cudaGetSymbolAddress((void**)&pZ, g_z);

    static cudaStream_t s1 = nullptr, s2 = nullptr;
    static cudaEvent_t evRoot = nullptr, evWp = nullptr, evWo = nullptr;
    if (!s1) {
        cudaStreamCreateWithFlags(&s1, cudaStreamNonBlocking);
        cudaStreamCreateWithFlags(&s2, cudaStreamNonBlocking);
        cudaEventCreateWithFlags(&evRoot, cudaEventDisableTiming);
        cudaEventCreateWithFlags(&evWp, cudaEventDisableTiming);
        cudaEventCreateWithFlags(&evWo, cudaEventDisableTiming);
        cudaFuncSetAttribute((const void*)gemm_f16<true>,
                             cudaFuncAttributeMaxDynamicSharedMemorySize, GSMEM1);
        cudaFuncSetAttribute((const void*)gemm_f16<false>,
                             cudaFuncAttributeMaxDynamicSharedMemorySize, GSMEM1);
    }

    cudaEventRecord(evRoot, 0);
    cudaStreamWaitEvent(s1, evRoot, 0);
    cudaStreamWaitEvent(s2, evRoot, 0);

    convQf16<<<(NTOK * QDIM / 4 + 255) / 256, 256>>>(query, pQ);
    transConvF16<<<dim3(PCOLS / 32, QDIM / 32), dim3(32, 8), 0, s1>>>(Wp, pWpT, QDIM, PCOLS);
    transConvF16<<<dim3(QDIM / 32, PCOLS / 32), dim3(32, 8), 0, s2>>>(Wo, pWoT, PCOLS, QDIM);

    cudaEventRecord(evWp, s1);
    cudaStreamWaitEvent(0, evWp, 0);

    // GEMM1: params(fp16) = q @ Wp + bp  (fp16 1-pass, K=256 -> 8 chunks)
    gemm_f16<true><<<dim3(PCOLS / 128, 29, 1), 256, GSMEM1>>>(
        pQ, pWpT, pParams, bp, NTOK, QDIM, QDIM, PCOLS, 8, 0);

    midkernel<<<NTOK * 4, 128>>>(x, pParams, pZ);

    cudaEventRecord(evWo, s2);
    cudaStreamWaitEvent(0, evWo, 0);

    // GEMM3: part[z] = Z[:, z*1024:(z+1)*1024] @ Wo-chunk  (fp16 1-pass)
    gemm_f16<false><<<dim3(QDIM / 128, 29, SPLITK), 256, GSMEM1>>>(
        pZ, pWoT, pPart, nullptr,
        NTOK, PCOLS, PCOLS, QDIM, (PCOLS / SPLITK) / 32, (int)((size_t)NTOK * QDIM));

    finalReduce<<<(NTOK * QDIM + 255) / 256, 256>>>(pPart, query, bo, out);
}